// round 9
// baseline (speedup 1.0000x reference)
#include <cuda_runtime.h>

// ---------------- problem constants (fixed by setup_inputs) ----------------
#define MAXN 100000
#define MAXE 1600000
#define HDIM 128
#define VDIM 256
#define BN_EPS 1e-5f

// ---------------- device scratch (static allocation; no cudaMalloc) --------
__device__ float d_deg[MAXN];
__device__ float d_dis[MAXN];
__device__ float d_self[MAXN];
__device__ int   d_cnt[MAXN];
__device__ int   d_rowptr[MAXN];
__device__ int   d_cursor[MAXN];
__device__ int2  d_edge[MAXE];          // .x = src row, .y = bits of norm weight
__device__ int   d_bsums[128];
__device__ int   d_is64;                // 1 if edge_index buffer is int64
__device__ float d_H  [(size_t)MAXN * HDIM];
__device__ float d_RES[(size_t)MAXN * HDIM];
__device__ float d_A  [(size_t)MAXN * HDIM];
__device__ float d_B  [(size_t)MAXN * HDIM];
__device__ float d_t  [MAXN];
__device__ float d_sc1[HDIM], d_sh1[HDIM], d_sc2[HDIM], d_sh2[HDIM];

// ---------------- edge_index dtype detection --------------------------------
// JAX with x64 disabled silently makes "int64" arrays int32. Detect by
// interpreting a prefix as int64: genuine int64 node ids are all in [0,n);
// an int32 buffer read as int64 fuses pairs -> astronomically large values.
__global__ void k_dtype(const void* ei, int E, int n) {
    __shared__ int bad;
    if (threadIdx.x == 0) bad = 0;
    __syncthreads();
    const long long* p = (const long long*)ei;
    int k = min(2 * E, 2048);           // 16KB max, safe for either dtype
    for (int i = threadIdx.x; i < k; i += blockDim.x) {
        long long v = p[i];
        if (v < 0 || v >= (long long)n) bad = 1;
    }
    __syncthreads();
    if (threadIdx.x == 0) d_is64 = bad ? 0 : 1;
}

__device__ __forceinline__ int edge_at(const void* ei, size_t idx, int is64) {
    return is64 ? (int)((const long long*)ei)[idx]
                : ((const int*)ei)[idx];
}

// ---------------- graph preprocessing --------------------------------------
__global__ void k_init(int n) {
    int i = blockIdx.x * blockDim.x + threadIdx.x;
    if (i < n) { d_deg[i] = 1.0f; d_cnt[i] = 0; }   // 1.0f = self-loop weight
}

__global__ void k_degcnt(const void* __restrict__ ei,
                         const float* __restrict__ ew, int E) {
    int e = blockIdx.x * blockDim.x + threadIdx.x;
    if (e < E) {
        int is64 = d_is64;
        int c = edge_at(ei, (size_t)E + e, is64);
        atomicAdd(&d_deg[c], ew[e]);
        atomicAdd(&d_cnt[c], 1);
    }
}

__global__ void k_dis(int n) {
    int i = blockIdx.x * blockDim.x + threadIdx.x;
    if (i < n) {
        float d = d_deg[i];
        d_dis[i]  = rsqrtf(d);
        d_self[i] = 1.0f / d;       // dis[i]^2, self-loop norm
    }
}

// exclusive scan of d_cnt -> d_rowptr (3-phase)
__global__ void k_scan1(int n) {
    __shared__ int s[1024];
    int i = blockIdx.x * 1024 + threadIdx.x;
    int v = (i < n) ? d_cnt[i] : 0;
    s[threadIdx.x] = v;
    __syncthreads();
    for (int off = 1; off < 1024; off <<= 1) {
        int t = (threadIdx.x >= off) ? s[threadIdx.x - off] : 0;
        __syncthreads();
        s[threadIdx.x] += t;
        __syncthreads();
    }
    if (i < n) d_rowptr[i] = s[threadIdx.x] - v;   // exclusive within block
    if (threadIdx.x == 1023) d_bsums[blockIdx.x] = s[1023];
}

__global__ void k_scan2(int nb) {
    __shared__ int s[128];
    int t = threadIdx.x;
    int v = (t < nb) ? d_bsums[t] : 0;
    s[t] = v;
    __syncthreads();
    for (int off = 1; off < 128; off <<= 1) {
        int u = (t >= off) ? s[t - off] : 0;
        __syncthreads();
        s[t] += u;
        __syncthreads();
    }
    if (t < nb) d_bsums[t] = s[t] - v;             // exclusive block offsets
}

__global__ void k_scan3(int n) {
    int i = blockIdx.x * 1024 + threadIdx.x;
    if (i < n) {
        int r = d_rowptr[i] + d_bsums[blockIdx.x];
        d_rowptr[i] = r;
        d_cursor[i] = r;
    }
}

__global__ void k_fill(const void* __restrict__ ei,
                       const float* __restrict__ ew, int E) {
    int e = blockIdx.x * blockDim.x + threadIdx.x;
    if (e < E) {
        int is64 = d_is64;
        int r = edge_at(ei, (size_t)e, is64);
        int c = edge_at(ei, (size_t)E + e, is64);
        int p = atomicAdd(&d_cursor[c], 1);
        float w = d_dis[r] * ew[e] * d_dis[c];
        d_edge[p] = make_int2(r, __float_as_int(w));
    }
}

// fold bias + BN(eval) into per-feature scale/shift
__global__ void k_bnprep(const float* b1, const float* g1, const float* be1,
                         const float* m1, const float* v1,
                         const float* b2, const float* g2, const float* be2,
                         const float* m2, const float* v2) {
    int i = threadIdx.x;
    if (i < HDIM) {
        float s1 = g1[i] * rsqrtf(v1[i] + BN_EPS);
        d_sc1[i] = s1;
        d_sh1[i] = (b1[i] - m1[i]) * s1 + be1[i];
        float s2 = g2[i] * rsqrtf(v2[i] + BN_EPS);
        d_sc2[i] = s2;
        d_sh2[i] = (b2[i] - m2[i]) * s2 + be2[i];
    }
}

// ---------------- fp32 tiled GEMM: C[N,128] = A[N,K] @ W[K,128] ------------
template<int K>
__global__ __launch_bounds__(256)
void k_gemm(const float* __restrict__ A, const float* __restrict__ W,
            float* __restrict__ C, int N) {
    __shared__ float As[32][128];   // k-major
    __shared__ float Ws[32][128];
    const int tid = threadIdx.x;
    const int tx = tid & 15;        // 16 col-groups of 8
    const int ty = tid >> 4;        // 16 row-groups of 8
    const int rowBase = blockIdx.x * 128;

    float acc[8][8];
#pragma unroll
    for (int i = 0; i < 8; i++)
#pragma unroll
        for (int j = 0; j < 8; j++) acc[i][j] = 0.0f;

    for (int k0 = 0; k0 < K; k0 += 32) {
        // A tile: 128 rows x 32 cols, coalesced float4 loads, transposed store
#pragma unroll
        for (int j = 0; j < 4; j++) {
            int f4 = tid + j * 256;         // 0..1023
            int ar = f4 >> 3;               // 0..127
            int ac = (f4 & 7) << 2;         // 0..28
            float4 v = make_float4(0.f, 0.f, 0.f, 0.f);
            int grow = rowBase + ar;
            if (grow < N)
                v = *reinterpret_cast<const float4*>(&A[(size_t)grow * K + k0 + ac]);
            As[ac + 0][ar] = v.x; As[ac + 1][ar] = v.y;
            As[ac + 2][ar] = v.z; As[ac + 3][ar] = v.w;
        }
        // W tile: 32 rows x 128 cols
#pragma unroll
        for (int j = 0; j < 4; j++) {
            int f4 = tid + j * 256;
            int wr = f4 >> 5;               // 0..31
            int wc = (f4 & 31) << 2;        // 0..124
            *reinterpret_cast<float4*>(&Ws[wr][wc]) =
                *reinterpret_cast<const float4*>(&W[(size_t)(k0 + wr) * HDIM + wc]);
        }
        __syncthreads();
#pragma unroll
        for (int k = 0; k < 32; k++) {
            float a[8], w[8];
            *reinterpret_cast<float4*>(&a[0]) = *reinterpret_cast<float4*>(&As[k][ty * 8]);
            *reinterpret_cast<float4*>(&a[4]) = *reinterpret_cast<float4*>(&As[k][ty * 8 + 4]);
            *reinterpret_cast<float4*>(&w[0]) = *reinterpret_cast<float4*>(&Ws[k][tx * 8]);
            *reinterpret_cast<float4*>(&w[4]) = *reinterpret_cast<float4*>(&Ws[k][tx * 8 + 4]);
#pragma unroll
            for (int i = 0; i < 8; i++)
#pragma unroll
                for (int j = 0; j < 8; j++)
                    acc[i][j] = fmaf(a[i], w[j], acc[i][j]);
        }
        __syncthreads();
    }
#pragma unroll
    for (int i = 0; i < 8; i++) {
        int grow = rowBase + ty * 8 + i;
        if (grow < N) {
            *reinterpret_cast<float4*>(&C[(size_t)grow * HDIM + tx * 8]) =
                *reinterpret_cast<float4*>(&acc[i][0]);
            *reinterpret_cast<float4*>(&C[(size_t)grow * HDIM + tx * 8 + 4]) =
                *reinterpret_cast<float4*>(&acc[i][4]);
        }
    }
}

// ---------------- SpMM gather: warp per destination node -------------------
// LAYER 1: out = relu(agg*sc1 + sh1)
// LAYER 2: out = relu((agg + res)*sc2 + sh2)
template<int LAYER>
__global__ __launch_bounds__(256)
void k_spmm(const float* __restrict__ Hbuf, const float* __restrict__ RES,
            float* __restrict__ O, int N) {
    int warp = (blockIdx.x * blockDim.x + threadIdx.x) >> 5;
    int lane = threadIdx.x & 31;
    if (warp >= N) return;
    const float4* H4 = reinterpret_cast<const float4*>(Hbuf);

    float sn = d_self[warp];
    float4 hv = H4[(size_t)warp * 32 + lane];
    float ax = hv.x * sn, ay = hv.y * sn, az = hv.z * sn, aw = hv.w * sn;

    int p = d_rowptr[warp];
    int e = p + d_cnt[warp];
    for (; p < e; p++) {
        int2 ed = d_edge[p];
        float w = __int_as_float(ed.y);
        float4 v = H4[(size_t)ed.x * 32 + lane];
        ax = fmaf(v.x, w, ax); ay = fmaf(v.y, w, ay);
        az = fmaf(v.z, w, az); aw = fmaf(v.w, w, aw);
    }

    const float* sc = (LAYER == 1) ? d_sc1 : d_sc2;
    const float* sh = (LAYER == 1) ? d_sh1 : d_sh2;
    float4 s4 = *reinterpret_cast<const float4*>(&sc[lane * 4]);
    float4 h4 = *reinterpret_cast<const float4*>(&sh[lane * 4]);

    if (LAYER == 2) {
        float4 r = reinterpret_cast<const float4*>(RES)[(size_t)warp * 32 + lane];
        ax += r.x; ay += r.y; az += r.z; aw += r.w;
    }
    float4 o;
    o.x = fmaxf(fmaf(ax, s4.x, h4.x), 0.f);
    o.y = fmaxf(fmaf(ay, s4.y, h4.y), 0.f);
    o.z = fmaxf(fmaf(az, s4.z, h4.z), 0.f);
    o.w = fmaxf(fmaf(aw, s4.w, h4.w), 0.f);
    reinterpret_cast<float4*>(O)[(size_t)warp * 32 + lane] = o;
}

// ---------------- layer 3: t[i] = dot(B[i,:], W3) --------------------------
__global__ __launch_bounds__(256)
void k_dot3(const float* __restrict__ B, const float* __restrict__ W3, int N) {
    int warp = (blockIdx.x * blockDim.x + threadIdx.x) >> 5;
    int lane = threadIdx.x & 31;
    if (warp >= N) return;
    float4 b = reinterpret_cast<const float4*>(B)[(size_t)warp * 32 + lane];
    float4 w = reinterpret_cast<const float4*>(W3)[lane];
    float s = b.x * w.x + b.y * w.y + b.z * w.z + b.w * w.w;
#pragma unroll
    for (int off = 16; off; off >>= 1) s += __shfl_down_sync(0xffffffffu, s, off);
    if (lane == 0) d_t[warp] = s;
}

__global__ void k_spmm3(float* __restrict__ out, const float* __restrict__ b3, int N) {
    int i = blockIdx.x * blockDim.x + threadIdx.x;
    if (i >= N) return;
    float acc = d_t[i] * d_self[i];
    int p = d_rowptr[i];
    int e = p + d_cnt[i];
    for (; p < e; p++) {
        int2 ed = d_edge[p];
        acc = fmaf(d_t[ed.x], __int_as_float(ed.y), acc);
    }
    out[i] = acc + b3[0];
}

// ---------------- launch ----------------------------------------------------
extern "C" void kernel_launch(void* const* d_in, const int* in_sizes, int n_in,
                              void* d_out, int out_size) {
    const float* x    = (const float*)d_in[0];
    const void*  ei   = d_in[1];                  // int32 or int64, auto-detected
    const float* ew   = (const float*)d_in[2];
    const float* W1   = (const float*)d_in[3];
    const float* b1   = (const float*)d_in[4];
    const float* W2   = (const float*)d_in[5];
    const float* b2   = (const float*)d_in[6];
    const float* W3   = (const float*)d_in[7];
    const float* b3   = (const float*)d_in[8];
    const float* Wres = (const float*)d_in[9];
    const float* g1 = (const float*)d_in[10];
    const float* be1 = (const float*)d_in[11];
    const float* m1 = (const float*)d_in[12];
    const float* v1 = (const float*)d_in[13];
    const float* g2 = (const float*)d_in[14];
    const float* be2 = (const float*)d_in[15];
    const float* m2 = (const float*)d_in[16];
    const float* v2 = (const float*)d_in[17];

    int N = out_size;           // 100000
    int E = in_sizes[2];        // 1600000 (edge_weight element count)
    float* out = (float*)d_out;

    float *pH, *pRES, *pA, *pB;
    cudaGetSymbolAddress((void**)&pH,   d_H);
    cudaGetSymbolAddress((void**)&pRES, d_RES);
    cudaGetSymbolAddress((void**)&pA,   d_A);
    cudaGetSymbolAddress((void**)&pB,   d_B);

    int nb    = (N + 1023) / 1024;
    int gN256 = (N + 255) / 256;
    int gE256 = (E + 255) / 256;
    int gGemm = (N + 127) / 128;
    int gWarp = (N + 7) / 8;        // warp-per-node, 256 thr/block

    // graph preprocessing (CSR by destination + symmetric norm)
    k_dtype <<<1, 256>>>(ei, E, N);
    k_init  <<<gN256, 256>>>(N);
    k_degcnt<<<gE256, 256>>>(ei, ew, E);
    k_dis   <<<gN256, 256>>>(N);
    k_scan1 <<<nb, 1024>>>(N);
    k_scan2 <<<1, 128>>>(nb);
    k_scan3 <<<nb, 1024>>>(N);
    k_fill  <<<gE256, 256>>>(ei, ew, E);
    k_bnprep<<<1, 128>>>(b1, g1, be1, m1, v1, b2, g2, be2, m2, v2);

    // layer 1 + residual branch
    k_gemm<VDIM><<<gGemm, 256>>>(x, W1,   pH,   N);
    k_gemm<VDIM><<<gGemm, 256>>>(x, Wres, pRES, N);
    k_spmm<1>   <<<gWarp, 256>>>(pH, nullptr, pA, N);

    // layer 2
    k_gemm<HDIM><<<gGemm, 256>>>(pA, W2, pH, N);
    k_spmm<2>   <<<gWarp, 256>>>(pH, pRES, pB, N);

    // layer 3 (scalar head)
    k_dot3 <<<gWarp, 256>>>(pB, W3, N);
    k_spmm3<<<gN256, 256>>>(out, b3, N);
}

// round 11
// speedup vs baseline: 1.5661x; 1.5661x over previous
#include <cuda_runtime.h>
#include <cuda_bf16.h>
#include <cstdint>

// ---------------- problem constants ----------------
#define MAXN 100000
#define MAXE 1600000
#define HDIM 128
#define VDIM 256
#define BN_EPS 1e-5f

// ---------------- device scratch (static; no cudaMalloc) --------
__device__ float d_deg[MAXN];
__device__ float d_dis[MAXN];
__device__ float d_self[MAXN];
__device__ int   d_cnt[MAXN];
__device__ int   d_rowptr[MAXN];
__device__ int   d_cursor[MAXN];
__device__ int2  d_edge[MAXE];
__device__ int   d_bsums[128];
__device__ int   d_is64;
__device__ float d_HR [(size_t)MAXN * 256];   // [x@W1 | x@Wres] fp32
__device__ float d_H2 [(size_t)MAXN * HDIM];  // layer-2 GEMM out fp32
__device__ float d_B  [(size_t)MAXN * HDIM];  // layer-2 activations fp32
__device__ float d_t  [MAXN];
__device__ float d_sc1[HDIM], d_sh1[HDIM], d_sc2[HDIM], d_sh2[HDIM];
// bf16 split operands
__device__ __nv_bfloat16 d_xhi[(size_t)MAXN * VDIM];
__device__ __nv_bfloat16 d_xlo[(size_t)MAXN * VDIM];
__device__ __nv_bfloat16 d_Ahi[(size_t)MAXN * HDIM];
__device__ __nv_bfloat16 d_Alo[(size_t)MAXN * HDIM];
__device__ __nv_bfloat16 d_W1hi[256 * 256], d_W1lo[256 * 256];   // [n][k] = [W1|Wres]^T
__device__ __nv_bfloat16 d_W2hi[128 * 128], d_W2lo[128 * 128];   // [n][k] = W2^T

// ---------------- PTX helpers (all baseline sm_80+ features) -----------------
__device__ __forceinline__ uint32_t smem_u32(const void* p) {
    uint32_t a;
    asm("{ .reg .u64 t; cvta.to.shared.u64 t, %1; cvt.u32.u64 %0, t; }"
        : "=r"(a) : "l"(p));
    return a;
}
__device__ __forceinline__ void ldm_x4(uint32_t a, uint32_t* r) {
    asm volatile("ldmatrix.sync.aligned.m8n8.x4.shared.b16 {%0,%1,%2,%3}, [%4];"
                 : "=r"(r[0]), "=r"(r[1]), "=r"(r[2]), "=r"(r[3]) : "r"(a));
}
__device__ __forceinline__ void mma16816(float* c, const uint32_t* a, const uint32_t* b) {
    asm volatile("mma.sync.aligned.m16n8k16.row.col.f32.bf16.bf16.f32 "
                 "{%0,%1,%2,%3}, {%4,%5,%6,%7}, {%8,%9}, {%0,%1,%2,%3};"
                 : "+f"(c[0]), "+f"(c[1]), "+f"(c[2]), "+f"(c[3])
                 : "r"(a[0]), "r"(a[1]), "r"(a[2]), "r"(a[3]), "r"(b[0]), "r"(b[1]));
}
__device__ __forceinline__ void cp16(uint32_t sa, const void* g) {
    asm volatile("cp.async.cg.shared.global [%0], [%1], 16;" :: "r"(sa), "l"(g));
}
__device__ __forceinline__ void cp_commit() {
    asm volatile("cp.async.commit_group;" ::: "memory");
}

__device__ __forceinline__ unsigned short bfbits(float f) {
    __nv_bfloat16 b = __float2bfloat16_rn(f);
    return *reinterpret_cast<unsigned short*>(&b);
}

// ---------------- edge_index dtype detection --------------------------------
__global__ void k_dtype(const void* ei, int E, int n) {
    __shared__ int bad;
    if (threadIdx.x == 0) bad = 0;
    __syncthreads();
    const long long* p = (const long long*)ei;
    int k = min(2 * E, 2048);
    for (int i = threadIdx.x; i < k; i += blockDim.x) {
        long long v = p[i];
        if (v < 0 || v >= (long long)n) bad = 1;
    }
    __syncthreads();
    if (threadIdx.x == 0) d_is64 = bad ? 0 : 1;
}
__device__ __forceinline__ int edge_at(const void* ei, size_t idx, int is64) {
    return is64 ? (int)((const long long*)ei)[idx] : ((const int*)ei)[idx];
}

// ---------------- graph preprocessing --------------------------------------
__global__ void k_init(int n) {
    int i = blockIdx.x * blockDim.x + threadIdx.x;
    if (i < n) { d_deg[i] = 1.0f; d_cnt[i] = 0; }
}
__global__ void k_degcnt(const void* __restrict__ ei, const float* __restrict__ ew, int E) {
    int e = blockIdx.x * blockDim.x + threadIdx.x;
    if (e < E) {
        int is64 = d_is64;
        int c = edge_at(ei, (size_t)E + e, is64);
        atomicAdd(&d_deg[c], ew[e]);
        atomicAdd(&d_cnt[c], 1);
    }
}
__global__ void k_dis(int n) {
    int i = blockIdx.x * blockDim.x + threadIdx.x;
    if (i < n) {
        float d = d_deg[i];
        d_dis[i] = rsqrtf(d);
        d_self[i] = 1.0f / d;
    }
}
__global__ void k_scan1(int n) {
    __shared__ int s[1024];
    int i = blockIdx.x * 1024 + threadIdx.x;
    int v = (i < n) ? d_cnt[i] : 0;
    s[threadIdx.x] = v;
    __syncthreads();
    for (int off = 1; off < 1024; off <<= 1) {
        int t = (threadIdx.x >= off) ? s[threadIdx.x - off] : 0;
        __syncthreads();
        s[threadIdx.x] += t;
        __syncthreads();
    }
    if (i < n) d_rowptr[i] = s[threadIdx.x] - v;
    if (threadIdx.x == 1023) d_bsums[blockIdx.x] = s[1023];
}
__global__ void k_scan2(int nb) {
    __shared__ int s[128];
    int t = threadIdx.x;
    int v = (t < nb) ? d_bsums[t] : 0;
    s[t] = v;
    __syncthreads();
    for (int off = 1; off < 128; off <<= 1) {
        int u = (t >= off) ? s[t - off] : 0;
        __syncthreads();
        s[t] += u;
        __syncthreads();
    }
    if (t < nb) d_bsums[t] = s[t] - v;
}
__global__ void k_scan3(int n) {
    int i = blockIdx.x * 1024 + threadIdx.x;
    if (i < n) {
        int r = d_rowptr[i] + d_bsums[blockIdx.x];
        d_rowptr[i] = r;
        d_cursor[i] = r;
    }
}
__global__ void k_fill(const void* __restrict__ ei, const float* __restrict__ ew, int E) {
    int e = blockIdx.x * blockDim.x + threadIdx.x;
    if (e < E) {
        int is64 = d_is64;
        int r = edge_at(ei, (size_t)e, is64);
        int c = edge_at(ei, (size_t)E + e, is64);
        int p = atomicAdd(&d_cursor[c], 1);
        float w = d_dis[r] * ew[e] * d_dis[c];
        d_edge[p] = make_int2(r, __float_as_int(w));
    }
}
__global__ void k_bnprep(const float* b1, const float* g1, const float* be1,
                         const float* m1, const float* v1,
                         const float* b2, const float* g2, const float* be2,
                         const float* m2, const float* v2) {
    int i = threadIdx.x;
    if (i < HDIM) {
        float s1 = g1[i] * rsqrtf(v1[i] + BN_EPS);
        d_sc1[i] = s1;
        d_sh1[i] = (b1[i] - m1[i]) * s1 + be1[i];
        float s2 = g2[i] * rsqrtf(v2[i] + BN_EPS);
        d_sc2[i] = s2;
        d_sh2[i] = (b2[i] - m2[i]) * s2 + be2[i];
    }
}

// ---------------- operand prep: fp32 -> bf16 hi/lo ---------------------------
__global__ void k_splitx(const float* __restrict__ x, size_t n4) {
    size_t i = (size_t)blockIdx.x * blockDim.x + threadIdx.x;
    if (i >= n4) return;
    float4 v = reinterpret_cast<const float4*>(x)[i];
    unsigned short h0 = bfbits(v.x), h1 = bfbits(v.y), h2 = bfbits(v.z), h3 = bfbits(v.w);
    __nv_bfloat16 b0 = *reinterpret_cast<__nv_bfloat16*>(&h0);
    __nv_bfloat16 b1 = *reinterpret_cast<__nv_bfloat16*>(&h1);
    __nv_bfloat16 b2 = *reinterpret_cast<__nv_bfloat16*>(&h2);
    __nv_bfloat16 b3 = *reinterpret_cast<__nv_bfloat16*>(&h3);
    unsigned short l0 = bfbits(v.x - __bfloat162float(b0));
    unsigned short l1 = bfbits(v.y - __bfloat162float(b1));
    unsigned short l2 = bfbits(v.z - __bfloat162float(b2));
    unsigned short l3 = bfbits(v.w - __bfloat162float(b3));
    uint2 hu = make_uint2((uint32_t)h0 | ((uint32_t)h1 << 16), (uint32_t)h2 | ((uint32_t)h3 << 16));
    uint2 lu = make_uint2((uint32_t)l0 | ((uint32_t)l1 << 16), (uint32_t)l2 | ((uint32_t)l3 << 16));
    reinterpret_cast<uint2*>(d_xhi)[i] = hu;
    reinterpret_cast<uint2*>(d_xlo)[i] = lu;
}
// W1|Wres -> transposed [n][k] (n<128: W1, n>=128: Wres), hi/lo
__global__ void k_prepw1(const float* __restrict__ W1, const float* __restrict__ Wres) {
    int i = blockIdx.x * blockDim.x + threadIdx.x;
    if (i >= 256 * 256) return;
    int n = i >> 8, k = i & 255;
    float w = (n < 128) ? W1[(size_t)k * 128 + n] : Wres[(size_t)k * 128 + (n - 128)];
    unsigned short h = bfbits(w);
    __nv_bfloat16 hb = *reinterpret_cast<__nv_bfloat16*>(&h);
    unsigned short l = bfbits(w - __bfloat162float(hb));
    d_W1hi[i] = hb;
    d_W1lo[i] = *reinterpret_cast<__nv_bfloat16*>(&l);
}
__global__ void k_prepw2(const float* __restrict__ W2) {
    int i = blockIdx.x * blockDim.x + threadIdx.x;
    if (i >= 128 * 128) return;
    int n = i >> 7, k = i & 127;
    float w = W2[(size_t)k * 128 + n];
    unsigned short h = bfbits(w);
    __nv_bfloat16 hb = *reinterpret_cast<__nv_bfloat16*>(&h);
    unsigned short l = bfbits(w - __bfloat162float(hb));
    d_W2hi[i] = hb;
    d_W2lo[i] = *reinterpret_cast<__nv_bfloat16*>(&l);
}

// ---------------- mma.sync split-bf16 GEMM -----------------------------------
// C[128 x 128 tile] fp32 = Ahi@Whi^T + Alo@Whi^T + Ahi@Wlo^T
// A: [N][K] bf16 row-major; W: [Ntot][K] bf16 row-major ("B^T"), K mult of 64.
// 256 threads = 8 warps, warp grid 2m x 4n, warp tile 64x32.
// SMEM per stage: Ahi|Alo|Whi|Wlo each [128][72] bf16 (144B rows) = 73728B; 2 stages.
#define LDSB 144              // bytes per SMEM row (64 bf16 + 8 pad)
#define MATB 18432            // bytes per matrix (128 * 144)
#define STAGEB 73728          // 4 matrices
#define TG_SMEM (2 * STAGEB)  // 147456

__global__ __launch_bounds__(256)
void k_tgemm(const __nv_bfloat16* __restrict__ Ahi, const __nv_bfloat16* __restrict__ Alo,
             const __nv_bfloat16* __restrict__ Whi, const __nv_bfloat16* __restrict__ Wlo,
             float* __restrict__ C, int N, int K, int Cstride) {
    extern __shared__ char smem[];
    const uint32_t sbase = smem_u32(smem);
    const int tid = threadIdx.x;
    const int lane = tid & 31;
    const int wid = tid >> 5;
    const int m_w = (wid >> 2) * 64;     // warp m offset in tile
    const int n_w = (wid & 3) * 32;      // warp n offset in tile
    const int rowBase = blockIdx.x * 128;
    const int nBase = blockIdx.y * 128;
    const int nch = K >> 6;

    float acc[4][4][4];
#pragma unroll
    for (int a = 0; a < 4; a++)
#pragma unroll
        for (int b = 0; b < 4; b++)
#pragma unroll
            for (int c = 0; c < 4; c++) acc[a][b][c] = 0.0f;

    // stage loader: 4096 x 16B cp.async (16 per thread)
    auto load_stage = [&](int buf, int k0) {
        uint32_t sb = sbase + buf * STAGEB;
#pragma unroll
        for (int i = 0; i < 16; i++) {
            int s = tid + i * 256;
            int m = s >> 10;           // 0:Ahi 1:Alo 2:Whi 3:Wlo
            int r = (s >> 3) & 127;
            int c = s & 7;
            const __nv_bfloat16* g;
            if (m == 0)      g = Ahi + (size_t)min(rowBase + r, N - 1) * K;
            else if (m == 1) g = Alo + (size_t)min(rowBase + r, N - 1) * K;
            else if (m == 2) g = Whi + (size_t)(nBase + r) * K;
            else             g = Wlo + (size_t)(nBase + r) * K;
            cp16(sb + m * MATB + r * LDSB + c * 16, g + k0 + c * 8);
        }
        cp_commit();
    };

    auto compute = [&](int buf) {
        uint32_t Ab = sbase + buf * STAGEB;
        uint32_t Wb = Ab + 2 * MATB;
#pragma unroll
        for (int kk = 0; kk < 64; kk += 16) {
            uint32_t ah[4][4], al[4][4], bh[2][4], bl[2][4];
#pragma unroll
            for (int mt = 0; mt < 4; mt++) {
                uint32_t ad = Ab + (m_w + mt * 16 + (lane & 15)) * LDSB
                                 + (kk + ((lane >> 4) << 3)) * 2;
                ldm_x4(ad, ah[mt]);
                ldm_x4(ad + MATB, al[mt]);
            }
#pragma unroll
            for (int p = 0; p < 2; p++) {
                int nloc = n_w + p * 16 + ((lane >> 4) << 3) + (lane & 7);
                uint32_t bd = Wb + nloc * LDSB + (kk + (((lane >> 3) & 1) << 3)) * 2;
                ldm_x4(bd, bh[p]);
                ldm_x4(bd + MATB, bl[p]);
            }
#pragma unroll
            for (int mt = 0; mt < 4; mt++)
#pragma unroll
                for (int nt = 0; nt < 4; nt++) {
                    const uint32_t* bhp = &bh[nt >> 1][(nt & 1) * 2];
                    const uint32_t* blp = &bl[nt >> 1][(nt & 1) * 2];
                    mma16816(acc[mt][nt], ah[mt], bhp);
                    mma16816(acc[mt][nt], al[mt], bhp);
                    mma16816(acc[mt][nt], ah[mt], blp);
                }
        }
    };

    load_stage(0, 0);
    if (nch > 1) load_stage(1, 64);

    for (int c = 0; c < nch; c++) {
        if (c + 1 == nch) asm volatile("cp.async.wait_group 0;" ::: "memory");
        else              asm volatile("cp.async.wait_group 1;" ::: "memory");
        __syncthreads();
        compute(c & 1);
        __syncthreads();
        if (c + 2 < nch) load_stage(c & 1, (c + 2) * 64);
    }

    // epilogue: direct register->global stores (c frag: t/4 row, 2*(t%4) col)
#pragma unroll
    for (int mt = 0; mt < 4; mt++) {
#pragma unroll
        for (int nt = 0; nt < 4; nt++) {
            int row0 = rowBase + m_w + mt * 16 + (lane >> 2);
            int col = nBase + n_w + nt * 8 + (lane & 3) * 2;
            if (row0 < N)
                *reinterpret_cast<float2*>(&C[(size_t)row0 * Cstride + col]) =
                    make_float2(acc[mt][nt][0], acc[mt][nt][1]);
            if (row0 + 8 < N)
                *reinterpret_cast<float2*>(&C[(size_t)(row0 + 8) * Cstride + col]) =
                    make_float2(acc[mt][nt][2], acc[mt][nt][3]);
        }
    }
}

// ---------------- SpMM layer 1: HR[:,0:128] -> relu(bn) -> bf16 hi/lo --------
__global__ __launch_bounds__(256)
void k_spmm1(const float* __restrict__ HR, int N) {
    int node = (blockIdx.x * blockDim.x + threadIdx.x) >> 5;
    int lane = threadIdx.x & 31;
    if (node >= N) return;
    const float4* H4 = reinterpret_cast<const float4*>(HR);   // row stride 64 float4

    float sn = d_self[node];
    float4 hv = H4[(size_t)node * 64 + lane];
    float ax = hv.x * sn, ay = hv.y * sn, az = hv.z * sn, aw = hv.w * sn;

    int p = d_rowptr[node];
    int e = p + d_cnt[node];
    for (; p < e; p++) {
        int2 ed = d_edge[p];
        float w = __int_as_float(ed.y);
        float4 v = H4[(size_t)ed.x * 64 + lane];
        ax = fmaf(v.x, w, ax); ay = fmaf(v.y, w, ay);
        az = fmaf(v.z, w, az); aw = fmaf(v.w, w, aw);
    }
    float4 s4 = *reinterpret_cast<const float4*>(&d_sc1[lane * 4]);
    float4 h4 = *reinterpret_cast<const float4*>(&d_sh1[lane * 4]);
    float o0 = fmaxf(fmaf(ax, s4.x, h4.x), 0.f);
    float o1 = fmaxf(fmaf(ay, s4.y, h4.y), 0.f);
    float o2 = fmaxf(fmaf(az, s4.z, h4.z), 0.f);
    float o3 = fmaxf(fmaf(aw, s4.w, h4.w), 0.f);

    unsigned short h0 = bfbits(o0), h1 = bfbits(o1), h2 = bfbits(o2), h3 = bfbits(o3);
    __nv_bfloat16 b0 = *reinterpret_cast<__nv_bfloat16*>(&h0);
    __nv_bfloat16 b1 = *reinterpret_cast<__nv_bfloat16*>(&h1);
    __nv_bfloat16 b2 = *reinterpret_cast<__nv_bfloat16*>(&h2);
    __nv_bfloat16 b3 = *reinterpret_cast<__nv_bfloat16*>(&h3);
    unsigned short l0 = bfbits(o0 - __bfloat162float(b0));
    unsigned short l1 = bfbits(o1 - __bfloat162float(b1));
    unsigned short l2 = bfbits(o2 - __bfloat162float(b2));
    unsigned short l3 = bfbits(o3 - __bfloat162float(b3));
    size_t oi = (size_t)node * 32 + lane;
    reinterpret_cast<uint2*>(d_Ahi)[oi] =
        make_uint2((uint32_t)h0 | ((uint32_t)h1 << 16), (uint32_t)h2 | ((uint32_t)h3 << 16));
    reinterpret_cast<uint2*>(d_Alo)[oi] =
        make_uint2((uint32_t)l0 | ((uint32_t)l1 << 16), (uint32_t)l2 | ((uint32_t)l3 << 16));
}

// ---------------- SpMM layer 2: H2 agg + residual(HR[:,128:256]) ------------
__global__ __launch_bounds__(256)
void k_spmm2(const float* __restrict__ H2, const float* __restrict__ HR, int N) {
    int node = (blockIdx.x * blockDim.x + threadIdx.x) >> 5;
    int lane = threadIdx.x & 31;
    if (node >= N) return;
    const float4* H4 = reinterpret_cast<const float4*>(H2);   // row stride 32 float4

    float sn = d_self[node];
    float4 hv = H4[(size_t)node * 32 + lane];
    float ax = hv.x * sn, ay = hv.y * sn, az = hv.z * sn, aw = hv.w * sn;

    int p = d_rowptr[node];
    int e = p + d_cnt[node];
    for (; p < e; p++) {
        int2 ed = d_edge[p];
        float w = __int_as_float(ed.y);
        float4 v = H4[(size_t)ed.x * 32 + lane];
        ax = fmaf(v.x, w, ax); ay = fmaf(v.y, w, ay);
        az = fmaf(v.z, w, az); aw = fmaf(v.w, w, aw);
    }
    float4 r = reinterpret_cast<const float4*>(HR)[(size_t)node * 64 + 32 + lane];
    ax += r.x; ay += r.y; az += r.z; aw += r.w;

    float4 s4 = *reinterpret_cast<const float4*>(&d_sc2[lane * 4]);
    float4 h4 = *reinterpret_cast<const float4*>(&d_sh2[lane * 4]);
    float4 o;
    o.x = fmaxf(fmaf(ax, s4.x, h4.x), 0.f);
    o.y = fmaxf(fmaf(ay, s4.y, h4.y), 0.f);
    o.z = fmaxf(fmaf(az, s4.z, h4.z), 0.f);
    o.w = fmaxf(fmaf(aw, s4.w, h4.w), 0.f);
    reinterpret_cast<float4*>(d_B)[(size_t)node * 32 + lane] = o;
}

// ---------------- layer 3 -----------------------------------------------------
__global__ __launch_bounds__(256)
void k_dot3(const float* __restrict__ W3, int N) {
    int warp = (blockIdx.x * blockDim.x + threadIdx.x) >> 5;
    int lane = threadIdx.x & 31;
    if (warp >= N) return;
    float4 b = reinterpret_cast<const float4*>(d_B)[(size_t)warp * 32 + lane];
    float4 w = reinterpret_cast<const float4*>(W3)[lane];
    float s = b.x * w.x + b.y * w.y + b.z * w.z + b.w * w.w;
#pragma unroll
    for (int off = 16; off; off >>= 1) s += __shfl_down_sync(0xffffffffu, s, off);
    if (lane == 0) d_t[warp] = s;
}

__global__ void k_spmm3(float* __restrict__ out, const float* __restrict__ b3, int N) {
    int i = blockIdx.x * blockDim.x + threadIdx.x;
    if (i >= N) return;
    float acc = d_t[i] * d_self[i];
    int p = d_rowptr[i];
    int e = p + d_cnt[i];
    for (; p < e; p++) {
        int2 ed = d_edge[p];
        acc = fmaf(d_t[ed.x], __int_as_float(ed.y), acc);
    }
    out[i] = acc + b3[0];
}

// ---------------- launch ------------------------------------------------------
extern "C" void kernel_launch(void* const* d_in, const int* in_sizes, int n_in,
                              void* d_out, int out_size) {
    const float* x    = (const float*)d_in[0];
    const void*  ei   = d_in[1];
    const float* ew   = (const float*)d_in[2];
    const float* W1   = (const float*)d_in[3];
    const float* b1   = (const float*)d_in[4];
    const float* W2   = (const float*)d_in[5];
    const float* b2   = (const float*)d_in[6];
    const float* W3   = (const float*)d_in[7];
    const float* b3   = (const float*)d_in[8];
    const float* Wres = (const float*)d_in[9];
    const float* g1 = (const float*)d_in[10];
    const float* be1 = (const float*)d_in[11];
    const float* m1 = (const float*)d_in[12];
    const float* v1 = (const float*)d_in[13];
    const float* g2 = (const float*)d_in[14];
    const float* be2 = (const float*)d_in[15];
    const float* m2 = (const float*)d_in[16];
    const float* v2 = (const float*)d_in[17];

    int N = out_size;
    int E = in_sizes[2];
    float* out = (float*)d_out;

    cudaFuncSetAttribute(k_tgemm, cudaFuncAttributeMaxDynamicSharedMemorySize, TG_SMEM);

    float *pHR, *pH2;
    __nv_bfloat16 *pxhi, *pxlo, *pAhi, *pAlo, *pW1hi, *pW1lo, *pW2hi, *pW2lo;
    cudaGetSymbolAddress((void**)&pHR,   d_HR);
    cudaGetSymbolAddress((void**)&pH2,   d_H2);
    cudaGetSymbolAddress((void**)&pxhi,  d_xhi);
    cudaGetSymbolAddress((void**)&pxlo,  d_xlo);
    cudaGetSymbolAddress((void**)&pAhi,  d_Ahi);
    cudaGetSymbolAddress((void**)&pAlo,  d_Alo);
    cudaGetSymbolAddress((void**)&pW1hi, d_W1hi);
    cudaGetSymbolAddress((void**)&pW1lo, d_W1lo);
    cudaGetSymbolAddress((void**)&pW2hi, d_W2hi);
    cudaGetSymbolAddress((void**)&pW2lo, d_W2lo);

    int nb    = (N + 1023) / 1024;
    int gN256 = (N + 255) / 256;
    int gE256 = (E + 255) / 256;
    int gWarp = (N + 7) / 8;
    int gRows = (N + 127) / 128;
    size_t n4 = (size_t)N * VDIM / 4;

    // graph preprocessing
    k_dtype <<<1, 256>>>(ei, E, N);
    k_init  <<<gN256, 256>>>(N);
    k_degcnt<<<gE256, 256>>>(ei, ew, E);
    k_dis   <<<gN256, 256>>>(N);
    k_scan1 <<<nb, 1024>>>(N);
    k_scan2 <<<1, 128>>>(nb);
    k_scan3 <<<nb, 1024>>>(N);
    k_fill  <<<gE256, 256>>>(ei, ew, E);
    k_bnprep<<<1, 128>>>(b1, g1, be1, m1, v1, b2, g2, be2, m2, v2);

    // operand prep
    k_splitx<<<(int)((n4 + 255) / 256), 256>>>(x, n4);
    k_prepw1<<<(256 * 256 + 255) / 256, 256>>>(W1, Wres);
    k_prepw2<<<(128 * 128 + 255) / 256, 256>>>(W2);

    // layer 1 + residual: HR = x @ [W1 | Wres]  (tensor cores, split bf16)
    k_tgemm<<<dim3(gRows, 2), 256, TG_SMEM>>>(pxhi, pxlo, pW1hi, pW1lo, pHR, N, VDIM, 256);
    k_spmm1<<<gWarp, 256>>>(pHR, N);

    // layer 2
    k_tgemm<<<dim3(gRows, 1), 256, TG_SMEM>>>(pAhi, pAlo, pW2hi, pW2lo, pH2, N, HDIM, 128);
    k_spmm2<<<gWarp, 256>>>(pH2, pHR, N);

    // layer 3
    k_dot3 <<<gWarp, 256>>>(W3, N);
    k_spmm3<<<gN256, 256>>>(out, b3, N);
}

// round 13
// speedup vs baseline: 1.6408x; 1.0477x over previous
#include <cuda_runtime.h>
#include <cuda_bf16.h>
#include <cstdint>

// ---------------- problem constants ----------------
#define MAXN 100000
#define MAXE 1600000
#define HDIM 128
#define VDIM 256
#define BN_EPS 1e-5f

// ---------------- device scratch (static; no cudaMalloc) --------
__device__ float d_deg[MAXN];
__device__ float d_dis[MAXN];
__device__ float d_self[MAXN];
__device__ int   d_cnt[MAXN];
__device__ int   d_rowptr[MAXN];
__device__ int   d_cursor[MAXN];
__device__ int2  d_edge[MAXE];
__device__ int   d_bsums[128];
__device__ int   d_is64;
__device__ float d_HR [(size_t)MAXN * 256];   // [x@W1 | x@Wres] fp32
__device__ float d_H2 [(size_t)MAXN * HDIM];  // layer-2 GEMM out fp32
__device__ float d_B  [(size_t)MAXN * HDIM];  // layer-2 activations fp32
__device__ float d_t  [MAXN];
__device__ float d_sc1[HDIM], d_sh1[HDIM], d_sc2[HDIM], d_sh2[HDIM];
// bf16 split operands
__device__ __nv_bfloat16 d_xhi[(size_t)MAXN * VDIM];
__device__ __nv_bfloat16 d_xlo[(size_t)MAXN * VDIM];
__device__ __nv_bfloat16 d_Ahi[(size_t)MAXN * HDIM];
__device__ __nv_bfloat16 d_Alo[(size_t)MAXN * HDIM];
__device__ __nv_bfloat16 d_W1hi[256 * 256], d_W1lo[256 * 256];   // [n][k] = [W1|Wres]^T
__device__ __nv_bfloat16 d_W2hi[128 * 128], d_W2lo[128 * 128];   // [n][k] = W2^T

// ---------------- PTX helpers (all baseline sm_80+ features) -----------------
__device__ __forceinline__ uint32_t smem_u32(const void* p) {
    uint32_t a;
    asm("{ .reg .u64 t; cvta.to.shared.u64 t, %1; cvt.u32.u64 %0, t; }"
        : "=r"(a) : "l"(p));
    return a;
}
__device__ __forceinline__ void ldm_x4(uint32_t a, uint32_t* r) {
    asm volatile("ldmatrix.sync.aligned.m8n8.x4.shared.b16 {%0,%1,%2,%3}, [%4];"
                 : "=r"(r[0]), "=r"(r[1]), "=r"(r[2]), "=r"(r[3]) : "r"(a));
}
__device__ __forceinline__ void mma16816(float* c, const uint32_t* a, const uint32_t* b) {
    asm volatile("mma.sync.aligned.m16n8k16.row.col.f32.bf16.bf16.f32 "
                 "{%0,%1,%2,%3}, {%4,%5,%6,%7}, {%8,%9}, {%0,%1,%2,%3};"
                 : "+f"(c[0]), "+f"(c[1]), "+f"(c[2]), "+f"(c[3])
                 : "r"(a[0]), "r"(a[1]), "r"(a[2]), "r"(a[3]), "r"(b[0]), "r"(b[1]));
}
__device__ __forceinline__ void cp16(uint32_t sa, const void* g) {
    asm volatile("cp.async.cg.shared.global [%0], [%1], 16;" :: "r"(sa), "l"(g));
}
__device__ __forceinline__ void cp_commit() {
    asm volatile("cp.async.commit_group;" ::: "memory");
}

__device__ __forceinline__ unsigned short bfbits(float f) {
    __nv_bfloat16 b = __float2bfloat16_rn(f);
    return *reinterpret_cast<unsigned short*>(&b);
}

// ---------------- edge_index dtype detection --------------------------------
__global__ void k_dtype(const void* ei, int E, int n) {
    __shared__ int bad;
    if (threadIdx.x == 0) bad = 0;
    __syncthreads();
    const long long* p = (const long long*)ei;
    int k = min(2 * E, 2048);
    for (int i = threadIdx.x; i < k; i += blockDim.x) {
        long long v = p[i];
        if (v < 0 || v >= (long long)n) bad = 1;
    }
    __syncthreads();
    if (threadIdx.x == 0) d_is64 = bad ? 0 : 1;
}
__device__ __forceinline__ int edge_at(const void* ei, size_t idx, int is64) {
    return is64 ? (int)((const long long*)ei)[idx] : ((const int*)ei)[idx];
}

// ---------------- graph preprocessing --------------------------------------
__global__ void k_init(int n) {
    int i = blockIdx.x * blockDim.x + threadIdx.x;
    if (i < n) { d_deg[i] = 1.0f; d_cnt[i] = 0; }
}
__global__ void k_degcnt(const void* __restrict__ ei, const float* __restrict__ ew, int E) {
    int e = blockIdx.x * blockDim.x + threadIdx.x;
    if (e < E) {
        int is64 = d_is64;
        int c = edge_at(ei, (size_t)E + e, is64);
        atomicAdd(&d_deg[c], ew[e]);
        atomicAdd(&d_cnt[c], 1);
    }
}
__global__ void k_dis(int n) {
    int i = blockIdx.x * blockDim.x + threadIdx.x;
    if (i < n) {
        float d = d_deg[i];
        d_dis[i] = rsqrtf(d);
        d_self[i] = 1.0f / d;
    }
}
__global__ void k_scan1(int n) {
    __shared__ int s[1024];
    int i = blockIdx.x * 1024 + threadIdx.x;
    int v = (i < n) ? d_cnt[i] : 0;
    s[threadIdx.x] = v;
    __syncthreads();
    for (int off = 1; off < 1024; off <<= 1) {
        int t = (threadIdx.x >= off) ? s[threadIdx.x - off] : 0;
        __syncthreads();
        s[threadIdx.x] += t;
        __syncthreads();
    }
    if (i < n) d_rowptr[i] = s[threadIdx.x] - v;
    if (threadIdx.x == 1023) d_bsums[blockIdx.x] = s[1023];
}
__global__ void k_scan2(int nb) {
    __shared__ int s[128];
    int t = threadIdx.x;
    int v = (t < nb) ? d_bsums[t] : 0;
    s[t] = v;
    __syncthreads();
    for (int off = 1; off < 128; off <<= 1) {
        int u = (t >= off) ? s[t - off] : 0;
        __syncthreads();
        s[t] += u;
        __syncthreads();
    }
    if (t < nb) d_bsums[t] = s[t] - v;
}
__global__ void k_scan3(int n) {
    int i = blockIdx.x * 1024 + threadIdx.x;
    if (i < n) {
        int r = d_rowptr[i] + d_bsums[blockIdx.x];
        d_rowptr[i] = r;
        d_cursor[i] = r;
    }
}
__global__ void k_fill(const void* __restrict__ ei, const float* __restrict__ ew, int E) {
    int e = blockIdx.x * blockDim.x + threadIdx.x;
    if (e < E) {
        int is64 = d_is64;
        int r = edge_at(ei, (size_t)e, is64);
        int c = edge_at(ei, (size_t)E + e, is64);
        int p = atomicAdd(&d_cursor[c], 1);
        float w = d_dis[r] * ew[e] * d_dis[c];
        d_edge[p] = make_int2(r, __float_as_int(w));
    }
}
__global__ void k_bnprep(const float* b1, const float* g1, const float* be1,
                         const float* m1, const float* v1,
                         const float* b2, const float* g2, const float* be2,
                         const float* m2, const float* v2) {
    int i = threadIdx.x;
    if (i < HDIM) {
        float s1 = g1[i] * rsqrtf(v1[i] + BN_EPS);
        d_sc1[i] = s1;
        d_sh1[i] = (b1[i] - m1[i]) * s1 + be1[i];
        float s2 = g2[i] * rsqrtf(v2[i] + BN_EPS);
        d_sc2[i] = s2;
        d_sh2[i] = (b2[i] - m2[i]) * s2 + be2[i];
    }
}

// ---------------- operand prep: fp32 -> bf16 hi/lo ---------------------------
__global__ void k_splitx(const float* __restrict__ x, size_t n4) {
    size_t i = (size_t)blockIdx.x * blockDim.x + threadIdx.x;
    if (i >= n4) return;
    float4 v = reinterpret_cast<const float4*>(x)[i];
    unsigned short h0 = bfbits(v.x), h1 = bfbits(v.y), h2 = bfbits(v.z), h3 = bfbits(v.w);
    __nv_bfloat16 b0 = *reinterpret_cast<__nv_bfloat16*>(&h0);
    __nv_bfloat16 b1 = *reinterpret_cast<__nv_bfloat16*>(&h1);
    __nv_bfloat16 b2 = *reinterpret_cast<__nv_bfloat16*>(&h2);
    __nv_bfloat16 b3 = *reinterpret_cast<__nv_bfloat16*>(&h3);
    unsigned short l0 = bfbits(v.x - __bfloat162float(b0));
    unsigned short l1 = bfbits(v.y - __bfloat162float(b1));
    unsigned short l2 = bfbits(v.z - __bfloat162float(b2));
    unsigned short l3 = bfbits(v.w - __bfloat162float(b3));
    uint2 hu = make_uint2((uint32_t)h0 | ((uint32_t)h1 << 16), (uint32_t)h2 | ((uint32_t)h3 << 16));
    uint2 lu = make_uint2((uint32_t)l0 | ((uint32_t)l1 << 16), (uint32_t)l2 | ((uint32_t)l3 << 16));
    reinterpret_cast<uint2*>(d_xhi)[i] = hu;
    reinterpret_cast<uint2*>(d_xlo)[i] = lu;
}
// W1|Wres -> transposed [n][k] (n<128: W1, n>=128: Wres), hi/lo
__global__ void k_prepw1(const float* __restrict__ W1, const float* __restrict__ Wres) {
    int i = blockIdx.x * blockDim.x + threadIdx.x;
    if (i >= 256 * 256) return;
    int n = i >> 8, k = i & 255;
    float w = (n < 128) ? W1[(size_t)k * 128 + n] : Wres[(size_t)k * 128 + (n - 128)];
    unsigned short h = bfbits(w);
    __nv_bfloat16 hb = *reinterpret_cast<__nv_bfloat16*>(&h);
    unsigned short l = bfbits(w - __bfloat162float(hb));
    d_W1hi[i] = hb;
    d_W1lo[i] = *reinterpret_cast<__nv_bfloat16*>(&l);
}
__global__ void k_prepw2(const float* __restrict__ W2) {
    int i = blockIdx.x * blockDim.x + threadIdx.x;
    if (i >= 128 * 128) return;
    int n = i >> 7, k = i & 127;
    float w = W2[(size_t)k * 128 + n];
    unsigned short h = bfbits(w);
    __nv_bfloat16 hb = *reinterpret_cast<__nv_bfloat16*>(&h);
    unsigned short l = bfbits(w - __bfloat162float(hb));
    d_W2hi[i] = hb;
    d_W2lo[i] = *reinterpret_cast<__nv_bfloat16*>(&l);
}

// ---------------- mma.sync split-bf16 GEMM -----------------------------------
// C[128 x 128 tile] fp32 = Ahi@Whi^T + Alo@Whi^T + Ahi@Wlo^T
// A: [N][K] bf16 row-major; W: [Ntot][K] bf16 row-major ("B^T"), K mult of 64.
// 256 threads = 8 warps, warp grid 2m x 4n, warp tile 64x32.
// SMEM per stage: Ahi|Alo|Whi|Wlo each [128][72] bf16 (144B rows) = 73728B; 2 stages.
#define LDSB 144              // bytes per SMEM row (64 bf16 + 8 pad)
#define MATB 18432            // bytes per matrix (128 * 144)
#define STAGEB 73728          // 4 matrices
#define TG_SMEM (2 * STAGEB)  // 147456

__global__ __launch_bounds__(256)
void k_tgemm(const __nv_bfloat16* __restrict__ Ahi, const __nv_bfloat16* __restrict__ Alo,
             const __nv_bfloat16* __restrict__ Whi, const __nv_bfloat16* __restrict__ Wlo,
             float* __restrict__ C, int N, int K, int Cstride, int nOfs) {
    extern __shared__ char smem[];
    const uint32_t sbase = smem_u32(smem);
    const int tid = threadIdx.x;
    const int lane = tid & 31;
    const int wid = tid >> 5;
    const int m_w = (wid >> 2) * 64;     // warp m offset in tile
    const int n_w = (wid & 3) * 32;      // warp n offset in tile
    const int rowBase = blockIdx.x * 128;
    const int nBase = blockIdx.y * 128 + nOfs;
    const int nch = K >> 6;

    float acc[4][4][4];
#pragma unroll
    for (int a = 0; a < 4; a++)
#pragma unroll
        for (int b = 0; b < 4; b++)
#pragma unroll
            for (int c = 0; c < 4; c++) acc[a][b][c] = 0.0f;

    // stage loader: 4096 x 16B cp.async (16 per thread)
    auto load_stage = [&](int buf, int k0) {
        uint32_t sb = sbase + buf * STAGEB;
#pragma unroll
        for (int i = 0; i < 16; i++) {
            int s = tid + i * 256;
            int m = s >> 10;           // 0:Ahi 1:Alo 2:Whi 3:Wlo
            int r = (s >> 3) & 127;
            int c = s & 7;
            const __nv_bfloat16* g;
            if (m == 0)      g = Ahi + (size_t)min(rowBase + r, N - 1) * K;
            else if (m == 1) g = Alo + (size_t)min(rowBase + r, N - 1) * K;
            else if (m == 2) g = Whi + (size_t)(nBase + r) * K;
            else             g = Wlo + (size_t)(nBase + r) * K;
            cp16(sb + m * MATB + r * LDSB + c * 16, g + k0 + c * 8);
        }
        cp_commit();
    };

    auto compute = [&](int buf) {
        uint32_t Ab = sbase + buf * STAGEB;
        uint32_t Wb = Ab + 2 * MATB;
#pragma unroll
        for (int kk = 0; kk < 64; kk += 16) {
            uint32_t ah[4][4], al[4][4], bh[2][4], bl[2][4];
#pragma unroll
            for (int mt = 0; mt < 4; mt++) {
                uint32_t ad = Ab + (m_w + mt * 16 + (lane & 15)) * LDSB
                                 + (kk + ((lane >> 4) << 3)) * 2;
                ldm_x4(ad, ah[mt]);
                ldm_x4(ad + MATB, al[mt]);
            }
#pragma unroll
            for (int p = 0; p < 2; p++) {
                int nloc = n_w + p * 16 + ((lane >> 4) << 3) + (lane & 7);
                uint32_t bd = Wb + nloc * LDSB + (kk + (((lane >> 3) & 1) << 3)) * 2;
                ldm_x4(bd, bh[p]);
                ldm_x4(bd + MATB, bl[p]);
            }
#pragma unroll
            for (int mt = 0; mt < 4; mt++)
#pragma unroll
                for (int nt = 0; nt < 4; nt++) {
                    const uint32_t* bhp = &bh[nt >> 1][(nt & 1) * 2];
                    const uint32_t* blp = &bl[nt >> 1][(nt & 1) * 2];
                    mma16816(acc[mt][nt], ah[mt], bhp);
                    mma16816(acc[mt][nt], al[mt], bhp);
                    mma16816(acc[mt][nt], ah[mt], blp);
                }
        }
    };

    load_stage(0, 0);
    if (nch > 1) load_stage(1, 64);

    for (int c = 0; c < nch; c++) {
        if (c + 1 == nch) asm volatile("cp.async.wait_group 0;" ::: "memory");
        else              asm volatile("cp.async.wait_group 1;" ::: "memory");
        __syncthreads();
        compute(c & 1);
        __syncthreads();
        if (c + 2 < nch) load_stage(c & 1, (c + 2) * 64);
    }

    // epilogue: direct register->global stores (c frag: t/4 row, 2*(t%4) col)
#pragma unroll
    for (int mt = 0; mt < 4; mt++) {
#pragma unroll
        for (int nt = 0; nt < 4; nt++) {
            int row0 = rowBase + m_w + mt * 16 + (lane >> 2);
            int col = nBase + n_w + nt * 8 + (lane & 3) * 2;
            if (row0 < N)
                *reinterpret_cast<float2*>(&C[(size_t)row0 * Cstride + col]) =
                    make_float2(acc[mt][nt][0], acc[mt][nt][1]);
            if (row0 + 8 < N)
                *reinterpret_cast<float2*>(&C[(size_t)(row0 + 8) * Cstride + col]) =
                    make_float2(acc[mt][nt][2], acc[mt][nt][3]);
        }
    }
}

// ---------------- SpMM layer 1: HR[:,0:128] -> relu(bn) -> bf16 hi/lo --------
__global__ __launch_bounds__(256)
void k_spmm1(const float* __restrict__ HR, int N) {
    int node = (blockIdx.x * blockDim.x + threadIdx.x) >> 5;
    int lane = threadIdx.x & 31;
    if (node >= N) return;
    const float4* H4 = reinterpret_cast<const float4*>(HR);   // row stride 64 float4

    float sn = d_self[node];
    float4 hv = H4[(size_t)node * 64 + lane];
    float ax = hv.x * sn, ay = hv.y * sn, az = hv.z * sn, aw = hv.w * sn;

    int p = d_rowptr[node];
    int e = p + d_cnt[node];
    for (; p < e; p++) {
        int2 ed = d_edge[p];
        float w = __int_as_float(ed.y);
        float4 v = H4[(size_t)ed.x * 64 + lane];
        ax = fmaf(v.x, w, ax); ay = fmaf(v.y, w, ay);
        az = fmaf(v.z, w, az); aw = fmaf(v.w, w, aw);
    }
    float4 s4 = *reinterpret_cast<const float4*>(&d_sc1[lane * 4]);
    float4 h4 = *reinterpret_cast<const float4*>(&d_sh1[lane * 4]);
    float o0 = fmaxf(fmaf(ax, s4.x, h4.x), 0.f);
    float o1 = fmaxf(fmaf(ay, s4.y, h4.y), 0.f);
    float o2 = fmaxf(fmaf(az, s4.z, h4.z), 0.f);
    float o3 = fmaxf(fmaf(aw, s4.w, h4.w), 0.f);

    unsigned short h0 = bfbits(o0), h1 = bfbits(o1), h2 = bfbits(o2), h3 = bfbits(o3);
    __nv_bfloat16 b0 = *reinterpret_cast<__nv_bfloat16*>(&h0);
    __nv_bfloat16 b1 = *reinterpret_cast<__nv_bfloat16*>(&h1);
    __nv_bfloat16 b2 = *reinterpret_cast<__nv_bfloat16*>(&h2);
    __nv_bfloat16 b3 = *reinterpret_cast<__nv_bfloat16*>(&h3);
    unsigned short l0 = bfbits(o0 - __bfloat162float(b0));
    unsigned short l1 = bfbits(o1 - __bfloat162float(b1));
    unsigned short l2 = bfbits(o2 - __bfloat162float(b2));
    unsigned short l3 = bfbits(o3 - __bfloat162float(b3));
    size_t oi = (size_t)node * 32 + lane;
    reinterpret_cast<uint2*>(d_Ahi)[oi] =
        make_uint2((uint32_t)h0 | ((uint32_t)h1 << 16), (uint32_t)h2 | ((uint32_t)h3 << 16));
    reinterpret_cast<uint2*>(d_Alo)[oi] =
        make_uint2((uint32_t)l0 | ((uint32_t)l1 << 16), (uint32_t)l2 | ((uint32_t)l3 << 16));
}

// ---------------- SpMM layer 2: H2 agg + residual(HR[:,128:256]) ------------
__global__ __launch_bounds__(256)
void k_spmm2(const float* __restrict__ H2, const float* __restrict__ HR, int N) {
    int node = (blockIdx.x * blockDim.x + threadIdx.x) >> 5;
    int lane = threadIdx.x & 31;
    if (node >= N) return;
    const float4* H4 = reinterpret_cast<const float4*>(H2);   // row stride 32 float4

    float sn = d_self[node];
    float4 hv = H4[(size_t)node * 32 + lane];
    float ax = hv.x * sn, ay = hv.y * sn, az = hv.z * sn, aw = hv.w * sn;

    int p = d_rowptr[node];
    int e = p + d_cnt[node];
    for (; p < e; p++) {
        int2 ed = d_edge[p];
        float w = __int_as_float(ed.y);
        float4 v = H4[(size_t)ed.x * 32 + lane];
        ax = fmaf(v.x, w, ax); ay = fmaf(v.y, w, ay);
        az = fmaf(v.z, w, az); aw = fmaf(v.w, w, aw);
    }
    float4 r = reinterpret_cast<const float4*>(HR)[(size_t)node * 64 + 32 + lane];
    ax += r.x; ay += r.y; az += r.z; aw += r.w;

    float4 s4 = *reinterpret_cast<const float4*>(&d_sc2[lane * 4]);
    float4 h4 = *reinterpret_cast<const float4*>(&d_sh2[lane * 4]);
    float4 o;
    o.x = fmaxf(fmaf(ax, s4.x, h4.x), 0.f);
    o.y = fmaxf(fmaf(ay, s4.y, h4.y), 0.f);
    o.z = fmaxf(fmaf(az, s4.z, h4.z), 0.f);
    o.w = fmaxf(fmaf(aw, s4.w, h4.w), 0.f);
    reinterpret_cast<float4*>(d_B)[(size_t)node * 32 + lane] = o;
}

// ---------------- layer 3 -----------------------------------------------------
__global__ __launch_bounds__(256)
void k_dot3(const float* __restrict__ W3, int N) {
    int warp = (blockIdx.x * blockDim.x + threadIdx.x) >> 5;
    int lane = threadIdx.x & 31;
    if (warp >= N) return;
    float4 b = reinterpret_cast<const float4*>(d_B)[(size_t)warp * 32 + lane];
    float4 w = reinterpret_cast<const float4*>(W3)[lane];
    float s = b.x * w.x + b.y * w.y + b.z * w.z + b.w * w.w;
#pragma unroll
    for (int off = 16; off; off >>= 1) s += __shfl_down_sync(0xffffffffu, s, off);
    if (lane == 0) d_t[warp] = s;
}

__global__ void k_spmm3(float* __restrict__ out, const float* __restrict__ b3, int N) {
    int i = blockIdx.x * blockDim.x + threadIdx.x;
    if (i >= N) return;
    float acc = d_t[i] * d_self[i];
    int p = d_rowptr[i];
    int e = p + d_cnt[i];
    for (; p < e; p++) {
        int2 ed = d_edge[p];
        acc = fmaf(d_t[ed.x], __int_as_float(ed.y), acc);
    }
    out[i] = acc + b3[0];
}

// ---------------- launch ------------------------------------------------------
extern "C" void kernel_launch(void* const* d_in, const int* in_sizes, int n_in,
                              void* d_out, int out_size) {
    const float* x    = (const float*)d_in[0];
    const void*  ei   = d_in[1];
    const float* ew   = (const float*)d_in[2];
    const float* W1   = (const float*)d_in[3];
    const float* b1   = (const float*)d_in[4];
    const float* W2   = (const float*)d_in[5];
    const float* b2   = (const float*)d_in[6];
    const float* W3   = (const float*)d_in[7];
    const float* b3   = (const float*)d_in[8];
    const float* Wres = (const float*)d_in[9];
    const float* g1 = (const float*)d_in[10];
    const float* be1 = (const float*)d_in[11];
    const float* m1 = (const float*)d_in[12];
    const float* v1 = (const float*)d_in[13];
    const float* g2 = (const float*)d_in[14];
    const float* be2 = (const float*)d_in[15];
    const float* m2 = (const float*)d_in[16];
    const float* v2 = (const float*)d_in[17];

    int N = out_size;
    int E = in_sizes[2];
    float* out = (float*)d_out;

    // one-time host resources (created on the non-captured correctness call)
    static cudaStream_t s_pre = nullptr, s_aux = nullptr;
    static cudaEvent_t evRoot = nullptr, evPre = nullptr, evX = nullptr, evB = nullptr;
    if (!s_pre) {
        cudaStreamCreateWithFlags(&s_pre, cudaStreamNonBlocking);
        cudaStreamCreateWithFlags(&s_aux, cudaStreamNonBlocking);
        cudaEventCreateWithFlags(&evRoot, cudaEventDisableTiming);
        cudaEventCreateWithFlags(&evPre,  cudaEventDisableTiming);
        cudaEventCreateWithFlags(&evX,    cudaEventDisableTiming);
        cudaEventCreateWithFlags(&evB,    cudaEventDisableTiming);
        cudaFuncSetAttribute(k_tgemm, cudaFuncAttributeMaxDynamicSharedMemorySize, TG_SMEM);
    }

    float *pHR, *pH2;
    __nv_bfloat16 *pxhi, *pxlo, *pAhi, *pAlo, *pW1hi, *pW1lo, *pW2hi, *pW2lo;
    cudaGetSymbolAddress((void**)&pHR,   d_HR);
    cudaGetSymbolAddress((void**)&pH2,   d_H2);
    cudaGetSymbolAddress((void**)&pxhi,  d_xhi);
    cudaGetSymbolAddress((void**)&pxlo,  d_xlo);
    cudaGetSymbolAddress((void**)&pAhi,  d_Ahi);
    cudaGetSymbolAddress((void**)&pAlo,  d_Alo);
    cudaGetSymbolAddress((void**)&pW1hi, d_W1hi);
    cudaGetSymbolAddress((void**)&pW1lo, d_W1lo);
    cudaGetSymbolAddress((void**)&pW2hi, d_W2hi);
    cudaGetSymbolAddress((void**)&pW2lo, d_W2lo);

    int nb    = (N + 1023) / 1024;
    int gN256 = (N + 255) / 256;
    int gE256 = (E + 255) / 256;
    int gWarp = (N + 7) / 8;
    int gRows = (N + 127) / 128;
    size_t n4 = (size_t)N * VDIM / 4;

    // ---- fork: preprocessing on s_pre, aux GEMM on s_aux, rest on legacy ----
    cudaEventRecord(evRoot, 0);
    cudaStreamWaitEvent(s_pre, evRoot, 0);

    // s_pre: CSR build + norm + BN prep (independent of x/W path)
    k_dtype <<<1, 256, 0, s_pre>>>(ei, E, N);
    k_init  <<<gN256, 256, 0, s_pre>>>(N);
    k_degcnt<<<gE256, 256, 0, s_pre>>>(ei, ew, E);
    k_dis   <<<gN256, 256, 0, s_pre>>>(N);
    k_scan1 <<<nb, 1024, 0, s_pre>>>(N);
    k_scan2 <<<1, 128, 0, s_pre>>>(nb);
    k_scan3 <<<nb, 1024, 0, s_pre>>>(N);
    k_fill  <<<gE256, 256, 0, s_pre>>>(ei, ew, E);
    k_bnprep<<<1, 128, 0, s_pre>>>(b1, g1, be1, m1, v1, b2, g2, be2, m2, v2);
    cudaEventRecord(evPre, s_pre);

    // legacy: operand prep
    k_splitx<<<(int)((n4 + 255) / 256), 256>>>(x, n4);
    k_prepw1<<<(256 * 256 + 255) / 256, 256>>>(W1, Wres);
    k_prepw2<<<(128 * 128 + 255) / 256, 256>>>(W2);
    cudaEventRecord(evX, 0);

    // s_aux: residual GEMM half (x @ Wres -> HR cols 128..255), overlaps S1
    cudaStreamWaitEvent(s_aux, evX, 0);
    k_tgemm<<<dim3(gRows, 1), 256, TG_SMEM, s_aux>>>(pxhi, pxlo, pW1hi, pW1lo,
                                                     pHR, N, VDIM, 256, 128);
    cudaEventRecord(evB, s_aux);

    // legacy: main GEMM half (x @ W1 -> HR cols 0..127)
    k_tgemm<<<dim3(gRows, 1), 256, TG_SMEM>>>(pxhi, pxlo, pW1hi, pW1lo,
                                              pHR, N, VDIM, 256, 0);

    // join preprocessing, then layer-1 aggregation
    cudaStreamWaitEvent(0, evPre, 0);
    k_spmm1<<<gWarp, 256>>>(pHR, N);

    // layer 2 GEMM
    k_tgemm<<<dim3(gRows, 1), 256, TG_SMEM>>>(pAhi, pAlo, pW2hi, pW2lo,
                                              pH2, N, HDIM, 128, 0);

    // join residual half, then layer-2 aggregation
    cudaStreamWaitEvent(0, evB, 0);
    k_spmm2<<<gWarp, 256>>>(pH2, pHR, N);

    // layer 3
    k_dot3 <<<gWarp, 256>>>(W3, N);
    k_spmm3<<<gN256, 256>>>(out, b3, N);
}

// round 14
// speedup vs baseline: 1.6843x; 1.0265x over previous
#include <cuda_runtime.h>
#include <cuda_bf16.h>
#include <cstdint>

// ---------------- problem constants ----------------
#define MAXN 100000
#define MAXE 1600000
#define HDIM 128
#define VDIM 256
#define BN_EPS 1e-5f

// ---------------- device scratch (static; no cudaMalloc) --------
__device__ float d_deg[MAXN];
__device__ float d_dis[MAXN];
__device__ float d_self[MAXN];
__device__ int   d_cnt[MAXN];
__device__ int   d_rowptr[MAXN];
__device__ int   d_cursor[MAXN];
__device__ int2  d_edge[MAXE];
__device__ int   d_bsums[128];
__device__ int   d_is64;
__device__ float d_HR [(size_t)MAXN * 256];   // [x@W1 | x@Wres] fp32
__device__ float d_H2 [(size_t)MAXN * HDIM];  // layer-2 GEMM out fp32
__device__ float d_t  [MAXN];
__device__ float d_sc1[HDIM], d_sh1[HDIM], d_sc2[HDIM], d_sh2[HDIM];
// bf16 split operands
__device__ __nv_bfloat16 d_xhi[(size_t)MAXN * VDIM];
__device__ __nv_bfloat16 d_xlo[(size_t)MAXN * VDIM];
__device__ __nv_bfloat16 d_Ahi[(size_t)MAXN * HDIM];
__device__ __nv_bfloat16 d_Alo[(size_t)MAXN * HDIM];
__device__ __nv_bfloat16 d_W1hi[256 * 256], d_W1lo[256 * 256];   // [n][k] = [W1|Wres]^T
__device__ __nv_bfloat16 d_W2hi[128 * 128], d_W2lo[128 * 128];   // [n][k] = W2^T

// ---------------- PTX helpers (all baseline sm_80+ features) -----------------
__device__ __forceinline__ uint32_t smem_u32(const void* p) {
    uint32_t a;
    asm("{ .reg .u64 t; cvta.to.shared.u64 t, %1; cvt.u32.u64 %0, t; }"
        : "=r"(a) : "l"(p));
    return a;
}
__device__ __forceinline__ void ldm_x4(uint32_t a, uint32_t* r) {
    asm volatile("ldmatrix.sync.aligned.m8n8.x4.shared.b16 {%0,%1,%2,%3}, [%4];"
                 : "=r"(r[0]), "=r"(r[1]), "=r"(r[2]), "=r"(r[3]) : "r"(a));
}
__device__ __forceinline__ void mma16816(float* c, const uint32_t* a, const uint32_t* b) {
    asm volatile("mma.sync.aligned.m16n8k16.row.col.f32.bf16.bf16.f32 "
                 "{%0,%1,%2,%3}, {%4,%5,%6,%7}, {%8,%9}, {%0,%1,%2,%3};"
                 : "+f"(c[0]), "+f"(c[1]), "+f"(c[2]), "+f"(c[3])
                 : "r"(a[0]), "r"(a[1]), "r"(a[2]), "r"(a[3]), "r"(b[0]), "r"(b[1]));
}
__device__ __forceinline__ void cp16(uint32_t sa, const void* g) {
    asm volatile("cp.async.cg.shared.global [%0], [%1], 16;" :: "r"(sa), "l"(g));
}
__device__ __forceinline__ void cp_commit() {
    asm volatile("cp.async.commit_group;" ::: "memory");
}

__device__ __forceinline__ unsigned short bfbits(float f) {
    __nv_bfloat16 b = __float2bfloat16_rn(f);
    return *reinterpret_cast<unsigned short*>(&b);
}

// ---------------- edge_index dtype detection --------------------------------
__global__ void k_dtype(const void* ei, int E, int n) {
    __shared__ int bad;
    if (threadIdx.x == 0) bad = 0;
    __syncthreads();
    const long long* p = (const long long*)ei;
    int k = min(2 * E, 2048);
    for (int i = threadIdx.x; i < k; i += blockDim.x) {
        long long v = p[i];
        if (v < 0 || v >= (long long)n) bad = 1;
    }
    __syncthreads();
    if (threadIdx.x == 0) d_is64 = bad ? 0 : 1;
}
__device__ __forceinline__ int edge_at(const void* ei, size_t idx, int is64) {
    return is64 ? (int)((const long long*)ei)[idx] : ((const int*)ei)[idx];
}

// ---------------- graph preprocessing --------------------------------------
__global__ void k_init(int n) {
    int i = blockIdx.x * blockDim.x + threadIdx.x;
    if (i < n) { d_deg[i] = 1.0f; d_cnt[i] = 0; }
}
__global__ void k_degcnt(const void* __restrict__ ei, const float* __restrict__ ew, int E) {
    int e = blockIdx.x * blockDim.x + threadIdx.x;
    if (e < E) {
        int is64 = d_is64;
        int c = edge_at(ei, (size_t)E + e, is64);
        atomicAdd(&d_deg[c], ew[e]);
        atomicAdd(&d_cnt[c], 1);
    }
}
__global__ void k_dis(int n) {
    int i = blockIdx.x * blockDim.x + threadIdx.x;
    if (i < n) {
        float d = d_deg[i];
        d_dis[i] = rsqrtf(d);
        d_self[i] = 1.0f / d;
    }
}
__global__ void k_scan1(int n) {
    __shared__ int s[1024];
    int i = blockIdx.x * 1024 + threadIdx.x;
    int v = (i < n) ? d_cnt[i] : 0;
    s[threadIdx.x] = v;
    __syncthreads();
    for (int off = 1; off < 1024; off <<= 1) {
        int t = (threadIdx.x >= off) ? s[threadIdx.x - off] : 0;
        __syncthreads();
        s[threadIdx.x] += t;
        __syncthreads();
    }
    if (i < n) d_rowptr[i] = s[threadIdx.x] - v;
    if (threadIdx.x == 1023) d_bsums[blockIdx.x] = s[1023];
}
__global__ void k_scan2(int nb) {
    __shared__ int s[128];
    int t = threadIdx.x;
    int v = (t < nb) ? d_bsums[t] : 0;
    s[t] = v;
    __syncthreads();
    for (int off = 1; off < 128; off <<= 1) {
        int u = (t >= off) ? s[t - off] : 0;
        __syncthreads();
        s[t] += u;
        __syncthreads();
    }
    if (t < nb) d_bsums[t] = s[t] - v;
}
__global__ void k_scan3(int n) {
    int i = blockIdx.x * 1024 + threadIdx.x;
    if (i < n) {
        int r = d_rowptr[i] + d_bsums[blockIdx.x];
        d_rowptr[i] = r;
        d_cursor[i] = r;
    }
}
__global__ void k_fill(const void* __restrict__ ei, const float* __restrict__ ew, int E) {
    int e = blockIdx.x * blockDim.x + threadIdx.x;
    if (e < E) {
        int is64 = d_is64;
        int r = edge_at(ei, (size_t)e, is64);
        int c = edge_at(ei, (size_t)E + e, is64);
        int p = atomicAdd(&d_cursor[c], 1);
        float w = d_dis[r] * ew[e] * d_dis[c];
        d_edge[p] = make_int2(r, __float_as_int(w));
    }
}
__global__ void k_bnprep(const float* b1, const float* g1, const float* be1,
                         const float* m1, const float* v1,
                         const float* b2, const float* g2, const float* be2,
                         const float* m2, const float* v2) {
    int i = threadIdx.x;
    if (i < HDIM) {
        float s1 = g1[i] * rsqrtf(v1[i] + BN_EPS);
        d_sc1[i] = s1;
        d_sh1[i] = (b1[i] - m1[i]) * s1 + be1[i];
        float s2 = g2[i] * rsqrtf(v2[i] + BN_EPS);
        d_sc2[i] = s2;
        d_sh2[i] = (b2[i] - m2[i]) * s2 + be2[i];
    }
}

// ---------------- operand prep: fp32 -> bf16 hi/lo ---------------------------
__global__ void k_splitx(const float* __restrict__ x, size_t n4) {
    size_t i = (size_t)blockIdx.x * blockDim.x + threadIdx.x;
    if (i >= n4) return;
    float4 v = reinterpret_cast<const float4*>(x)[i];
    unsigned short h0 = bfbits(v.x), h1 = bfbits(v.y), h2 = bfbits(v.z), h3 = bfbits(v.w);
    __nv_bfloat16 b0 = *reinterpret_cast<__nv_bfloat16*>(&h0);
    __nv_bfloat16 b1 = *reinterpret_cast<__nv_bfloat16*>(&h1);
    __nv_bfloat16 b2 = *reinterpret_cast<__nv_bfloat16*>(&h2);
    __nv_bfloat16 b3 = *reinterpret_cast<__nv_bfloat16*>(&h3);
    unsigned short l0 = bfbits(v.x - __bfloat162float(b0));
    unsigned short l1 = bfbits(v.y - __bfloat162float(b1));
    unsigned short l2 = bfbits(v.z - __bfloat162float(b2));
    unsigned short l3 = bfbits(v.w - __bfloat162float(b3));
    uint2 hu = make_uint2((uint32_t)h0 | ((uint32_t)h1 << 16), (uint32_t)h2 | ((uint32_t)h3 << 16));
    uint2 lu = make_uint2((uint32_t)l0 | ((uint32_t)l1 << 16), (uint32_t)l2 | ((uint32_t)l3 << 16));
    reinterpret_cast<uint2*>(d_xhi)[i] = hu;
    reinterpret_cast<uint2*>(d_xlo)[i] = lu;
}
// W1|Wres -> transposed [n][k] (n<128: W1, n>=128: Wres), hi/lo
__global__ void k_prepw1(const float* __restrict__ W1, const float* __restrict__ Wres) {
    int i = blockIdx.x * blockDim.x + threadIdx.x;
    if (i >= 256 * 256) return;
    int n = i >> 8, k = i & 255;
    float w = (n < 128) ? W1[(size_t)k * 128 + n] : Wres[(size_t)k * 128 + (n - 128)];
    unsigned short h = bfbits(w);
    __nv_bfloat16 hb = *reinterpret_cast<__nv_bfloat16*>(&h);
    unsigned short l = bfbits(w - __bfloat162float(hb));
    d_W1hi[i] = hb;
    d_W1lo[i] = *reinterpret_cast<__nv_bfloat16*>(&l);
}
__global__ void k_prepw2(const float* __restrict__ W2) {
    int i = blockIdx.x * blockDim.x + threadIdx.x;
    if (i >= 128 * 128) return;
    int n = i >> 7, k = i & 127;
    float w = W2[(size_t)k * 128 + n];
    unsigned short h = bfbits(w);
    __nv_bfloat16 hb = *reinterpret_cast<__nv_bfloat16*>(&h);
    unsigned short l = bfbits(w - __bfloat162float(hb));
    d_W2hi[i] = hb;
    d_W2lo[i] = *reinterpret_cast<__nv_bfloat16*>(&l);
}

// ---------------- mma.sync split-bf16 GEMM -----------------------------------
#define LDSB 144              // bytes per SMEM row (64 bf16 + 8 pad)
#define MATB 18432            // bytes per matrix (128 * 144)
#define STAGEB 73728          // 4 matrices
#define TG_SMEM (2 * STAGEB)  // 147456

__global__ __launch_bounds__(256)
void k_tgemm(const __nv_bfloat16* __restrict__ Ahi, const __nv_bfloat16* __restrict__ Alo,
             const __nv_bfloat16* __restrict__ Whi, const __nv_bfloat16* __restrict__ Wlo,
             float* __restrict__ C, int N, int K, int Cstride, int nOfs) {
    extern __shared__ char smem[];
    const uint32_t sbase = smem_u32(smem);
    const int tid = threadIdx.x;
    const int lane = tid & 31;
    const int wid = tid >> 5;
    const int m_w = (wid >> 2) * 64;
    const int n_w = (wid & 3) * 32;
    const int rowBase = blockIdx.x * 128;
    const int nBase = blockIdx.y * 128 + nOfs;
    const int nch = K >> 6;

    float acc[4][4][4];
#pragma unroll
    for (int a = 0; a < 4; a++)
#pragma unroll
        for (int b = 0; b < 4; b++)
#pragma unroll
            for (int c = 0; c < 4; c++) acc[a][b][c] = 0.0f;

    auto load_stage = [&](int buf, int k0) {
        uint32_t sb = sbase + buf * STAGEB;
#pragma unroll
        for (int i = 0; i < 16; i++) {
            int s = tid + i * 256;
            int m = s >> 10;           // 0:Ahi 1:Alo 2:Whi 3:Wlo
            int r = (s >> 3) & 127;
            int c = s & 7;
            const __nv_bfloat16* g;
            if (m == 0)      g = Ahi + (size_t)min(rowBase + r, N - 1) * K;
            else if (m == 1) g = Alo + (size_t)min(rowBase + r, N - 1) * K;
            else if (m == 2) g = Whi + (size_t)(nBase + r) * K;
            else             g = Wlo + (size_t)(nBase + r) * K;
            cp16(sb + m * MATB + r * LDSB + c * 16, g + k0 + c * 8);
        }
        cp_commit();
    };

    auto compute = [&](int buf) {
        uint32_t Ab = sbase + buf * STAGEB;
        uint32_t Wb = Ab + 2 * MATB;
#pragma unroll
        for (int kk = 0; kk < 64; kk += 16) {
            uint32_t ah[4][4], al[4][4], bh[2][4], bl[2][4];
#pragma unroll
            for (int mt = 0; mt < 4; mt++) {
                uint32_t ad = Ab + (m_w + mt * 16 + (lane & 15)) * LDSB
                                 + (kk + ((lane >> 4) << 3)) * 2;
                ldm_x4(ad, ah[mt]);
                ldm_x4(ad + MATB, al[mt]);
            }
#pragma unroll
            for (int p = 0; p < 2; p++) {
                int nloc = n_w + p * 16 + ((lane >> 4) << 3) + (lane & 7);
                uint32_t bd = Wb + nloc * LDSB + (kk + (((lane >> 3) & 1) << 3)) * 2;
                ldm_x4(bd, bh[p]);
                ldm_x4(bd + MATB, bl[p]);
            }
#pragma unroll
            for (int mt = 0; mt < 4; mt++)
#pragma unroll
                for (int nt = 0; nt < 4; nt++) {
                    const uint32_t* bhp = &bh[nt >> 1][(nt & 1) * 2];
                    const uint32_t* blp = &bl[nt >> 1][(nt & 1) * 2];
                    mma16816(acc[mt][nt], ah[mt], bhp);
                    mma16816(acc[mt][nt], al[mt], bhp);
                    mma16816(acc[mt][nt], ah[mt], blp);
                }
        }
    };

    load_stage(0, 0);
    if (nch > 1) load_stage(1, 64);

    for (int c = 0; c < nch; c++) {
        if (c + 1 == nch) asm volatile("cp.async.wait_group 0;" ::: "memory");
        else              asm volatile("cp.async.wait_group 1;" ::: "memory");
        __syncthreads();
        compute(c & 1);
        __syncthreads();
        if (c + 2 < nch) load_stage(c & 1, (c + 2) * 64);
    }

#pragma unroll
    for (int mt = 0; mt < 4; mt++) {
#pragma unroll
        for (int nt = 0; nt < 4; nt++) {
            int row0 = rowBase + m_w + mt * 16 + (lane >> 2);
            int col = nBase + n_w + nt * 8 + (lane & 3) * 2;
            if (row0 < N)
                *reinterpret_cast<float2*>(&C[(size_t)row0 * Cstride + col]) =
                    make_float2(acc[mt][nt][0], acc[mt][nt][1]);
            if (row0 + 8 < N)
                *reinterpret_cast<float2*>(&C[(size_t)(row0 + 8) * Cstride + col]) =
                    make_float2(acc[mt][nt][2], acc[mt][nt][3]);
        }
    }
}

// ---------------- SpMM layer 1: HR[:,0:128] -> relu(bn) -> bf16 hi/lo --------
__global__ __launch_bounds__(256)
void k_spmm1(const float* __restrict__ HR, int N) {
    int node = (blockIdx.x * blockDim.x + threadIdx.x) >> 5;
    int lane = threadIdx.x & 31;
    if (node >= N) return;
    const float4* H4 = reinterpret_cast<const float4*>(HR);   // row stride 64 float4

    float sn = d_self[node];
    float4 hv = H4[(size_t)node * 64 + lane];
    float ax = hv.x * sn, ay = hv.y * sn, az = hv.z * sn, aw = hv.w * sn;

    int p = d_rowptr[node];
    int e = p + d_cnt[node];
    for (; p < e; p++) {
        int2 ed = d_edge[p];
        float w = __int_as_float(ed.y);
        float4 v = H4[(size_t)ed.x * 64 + lane];
        ax = fmaf(v.x, w, ax); ay = fmaf(v.y, w, ay);
        az = fmaf(v.z, w, az); aw = fmaf(v.w, w, aw);
    }
    float4 s4 = *reinterpret_cast<const float4*>(&d_sc1[lane * 4]);
    float4 h4 = *reinterpret_cast<const float4*>(&d_sh1[lane * 4]);
    float o0 = fmaxf(fmaf(ax, s4.x, h4.x), 0.f);
    float o1 = fmaxf(fmaf(ay, s4.y, h4.y), 0.f);
    float o2 = fmaxf(fmaf(az, s4.z, h4.z), 0.f);
    float o3 = fmaxf(fmaf(aw, s4.w, h4.w), 0.f);

    unsigned short h0 = bfbits(o0), h1 = bfbits(o1), h2 = bfbits(o2), h3 = bfbits(o3);
    __nv_bfloat16 b0 = *reinterpret_cast<__nv_bfloat16*>(&h0);
    __nv_bfloat16 b1 = *reinterpret_cast<__nv_bfloat16*>(&h1);
    __nv_bfloat16 b2 = *reinterpret_cast<__nv_bfloat16*>(&h2);
    __nv_bfloat16 b3 = *reinterpret_cast<__nv_bfloat16*>(&h3);
    unsigned short l0 = bfbits(o0 - __bfloat162float(b0));
    unsigned short l1 = bfbits(o1 - __bfloat162float(b1));
    unsigned short l2 = bfbits(o2 - __bfloat162float(b2));
    unsigned short l3 = bfbits(o3 - __bfloat162float(b3));
    size_t oi = (size_t)node * 32 + lane;
    reinterpret_cast<uint2*>(d_Ahi)[oi] =
        make_uint2((uint32_t)h0 | ((uint32_t)h1 << 16), (uint32_t)h2 | ((uint32_t)h3 << 16));
    reinterpret_cast<uint2*>(d_Alo)[oi] =
        make_uint2((uint32_t)l0 | ((uint32_t)l1 << 16), (uint32_t)l2 | ((uint32_t)l3 << 16));
}

// ---- SpMM layer 2 + fused head dot: agg + res -> bn/relu -> dot(W3) -> d_t --
__global__ __launch_bounds__(256)
void k_spmm2(const float* __restrict__ H2, const float* __restrict__ HR,
             const float* __restrict__ W3, int N) {
    int node = (blockIdx.x * blockDim.x + threadIdx.x) >> 5;
    int lane = threadIdx.x & 31;
    if (node >= N) return;
    const float4* H4 = reinterpret_cast<const float4*>(H2);   // row stride 32 float4

    float sn = d_self[node];
    float4 hv = H4[(size_t)node * 32 + lane];
    float ax = hv.x * sn, ay = hv.y * sn, az = hv.z * sn, aw = hv.w * sn;

    int p = d_rowptr[node];
    int e = p + d_cnt[node];
    for (; p < e; p++) {
        int2 ed = d_edge[p];
        float w = __int_as_float(ed.y);
        float4 v = H4[(size_t)ed.x * 32 + lane];
        ax = fmaf(v.x, w, ax); ay = fmaf(v.y, w, ay);
        az = fmaf(v.z, w, az); aw = fmaf(v.w, w, aw);
    }
    float4 r = reinterpret_cast<const float4*>(HR)[(size_t)node * 64 + 32 + lane];
    ax += r.x; ay += r.y; az += r.z; aw += r.w;

    float4 s4 = *reinterpret_cast<const float4*>(&d_sc2[lane * 4]);
    float4 h4 = *reinterpret_cast<const float4*>(&d_sh2[lane * 4]);
    float o0 = fmaxf(fmaf(ax, s4.x, h4.x), 0.f);
    float o1 = fmaxf(fmaf(ay, s4.y, h4.y), 0.f);
    float o2 = fmaxf(fmaf(az, s4.z, h4.z), 0.f);
    float o3 = fmaxf(fmaf(aw, s4.w, h4.w), 0.f);

    // fused scalar head: dot with W3 + warp reduce
    float4 w3 = reinterpret_cast<const float4*>(W3)[lane];
    float s = o0 * w3.x + o1 * w3.y + o2 * w3.z + o3 * w3.w;
#pragma unroll
    for (int off = 16; off; off >>= 1) s += __shfl_down_sync(0xffffffffu, s, off);
    if (lane == 0) d_t[node] = s;
}

__global__ void k_spmm3(float* __restrict__ out, const float* __restrict__ b3, int N) {
    int i = blockIdx.x * blockDim.x + threadIdx.x;
    if (i >= N) return;
    float acc = d_t[i] * d_self[i];
    int p = d_rowptr[i];
    int e = p + d_cnt[i];
    for (; p < e; p++) {
        int2 ed = d_edge[p];
        acc = fmaf(d_t[ed.x], __int_as_float(ed.y), acc);
    }
    out[i] = acc + b3[0];
}

// ---------------- launch ------------------------------------------------------
extern "C" void kernel_launch(void* const* d_in, const int* in_sizes, int n_in,
                              void* d_out, int out_size) {
    const float* x    = (const float*)d_in[0];
    const void*  ei   = d_in[1];
    const float* ew   = (const float*)d_in[2];
    const float* W1   = (const float*)d_in[3];
    const float* b1   = (const float*)d_in[4];
    const float* W2   = (const float*)d_in[5];
    const float* b2   = (const float*)d_in[6];
    const float* W3   = (const float*)d_in[7];
    const float* b3   = (const float*)d_in[8];
    const float* Wres = (const float*)d_in[9];
    const float* g1 = (const float*)d_in[10];
    const float* be1 = (const float*)d_in[11];
    const float* m1 = (const float*)d_in[12];
    const float* v1 = (const float*)d_in[13];
    const float* g2 = (const float*)d_in[14];
    const float* be2 = (const float*)d_in[15];
    const float* m2 = (const float*)d_in[16];
    const float* v2 = (const float*)d_in[17];

    int N = out_size;
    int E = in_sizes[2];
    float* out = (float*)d_out;

    // one-time host resources (created on the non-captured correctness call)
    static cudaStream_t s_pre = nullptr, s_aux = nullptr;
    static cudaEvent_t evRoot = nullptr, evPre = nullptr, evA = nullptr, evB = nullptr;
    if (!s_pre) {
        cudaStreamCreateWithFlags(&s_pre, cudaStreamNonBlocking);
        cudaStreamCreateWithFlags(&s_aux, cudaStreamNonBlocking);
        cudaEventCreateWithFlags(&evRoot, cudaEventDisableTiming);
        cudaEventCreateWithFlags(&evPre,  cudaEventDisableTiming);
        cudaEventCreateWithFlags(&evA,    cudaEventDisableTiming);
        cudaEventCreateWithFlags(&evB,    cudaEventDisableTiming);
        cudaFuncSetAttribute(k_tgemm, cudaFuncAttributeMaxDynamicSharedMemorySize, TG_SMEM);
    }

    float *pHR, *pH2;
    __nv_bfloat16 *pxhi, *pxlo, *pAhi, *pAlo, *pW1hi, *pW1lo, *pW2hi, *pW2lo;
    cudaGetSymbolAddress((void**)&pHR,   d_HR);
    cudaGetSymbolAddress((void**)&pH2,   d_H2);
    cudaGetSymbolAddress((void**)&pxhi,  d_xhi);
    cudaGetSymbolAddress((void**)&pxlo,  d_xlo);
    cudaGetSymbolAddress((void**)&pAhi,  d_Ahi);
    cudaGetSymbolAddress((void**)&pAlo,  d_Alo);
    cudaGetSymbolAddress((void**)&pW1hi, d_W1hi);
    cudaGetSymbolAddress((void**)&pW1lo, d_W1lo);
    cudaGetSymbolAddress((void**)&pW2hi, d_W2hi);
    cudaGetSymbolAddress((void**)&pW2lo, d_W2lo);

    int nb    = (N + 1023) / 1024;
    int gN256 = (N + 255) / 256;
    int gE256 = (E + 255) / 256;
    int gWarp = (N + 7) / 8;
    int gRows = (N + 127) / 128;
    size_t n4 = (size_t)N * VDIM / 4;

    // ---- fork: preprocessing on s_pre; legacy does dense path ----
    cudaEventRecord(evRoot, 0);
    cudaStreamWaitEvent(s_pre, evRoot, 0);

    // s_pre: CSR build + norm + BN prep (independent of x/W path)
    k_dtype <<<1, 256, 0, s_pre>>>(ei, E, N);
    k_init  <<<gN256, 256, 0, s_pre>>>(N);
    k_degcnt<<<gE256, 256, 0, s_pre>>>(ei, ew, E);
    k_dis   <<<gN256, 256, 0, s_pre>>>(N);
    k_scan1 <<<nb, 1024, 0, s_pre>>>(N);
    k_scan2 <<<1, 128, 0, s_pre>>>(nb);
    k_scan3 <<<nb, 1024, 0, s_pre>>>(N);
    k_fill  <<<gE256, 256, 0, s_pre>>>(ei, ew, E);
    k_bnprep<<<1, 128, 0, s_pre>>>(b1, g1, be1, m1, v1, b2, g2, be2, m2, v2);
    cudaEventRecord(evPre, s_pre);

    // legacy: operand prep then G1a at full machine width
    k_splitx<<<(int)((n4 + 255) / 256), 256>>>(x, n4);
    k_prepw1<<<(256 * 256 + 255) / 256, 256>>>(W1, Wres);
    k_prepw2<<<(128 * 128 + 255) / 256, 256>>>(W2);

    // G1a: x @ W1 -> HR cols 0..127 (full machine, nothing concurrent)
    k_tgemm<<<dim3(gRows, 1), 256, TG_SMEM>>>(pxhi, pxlo, pW1hi, pW1lo,
                                              pHR, N, VDIM, 256, 0);
    cudaEventRecord(evA, 0);

    // s_aux: G1b (x @ Wres -> HR cols 128..255) AFTER G1a, overlapping SpMM-1
    // (tensor-bound G1b ∥ L2-gather-bound SpMM-1 — complementary pipes)
    cudaStreamWaitEvent(s_aux, evA, 0);
    k_tgemm<<<dim3(gRows, 1), 256, TG_SMEM, s_aux>>>(pxhi, pxlo, pW1hi, pW1lo,
                                                     pHR, N, VDIM, 256, 128);
    cudaEventRecord(evB, s_aux);

    // legacy: join preprocessing, then layer-1 aggregation (runs ∥ G1b)
    cudaStreamWaitEvent(0, evPre, 0);
    k_spmm1<<<gWarp, 256>>>(pHR, N);

    // layer 2 GEMM
    k_tgemm<<<dim3(gRows, 1), 256, TG_SMEM>>>(pAhi, pAlo, pW2hi, pW2lo,
                                              pH2, N, HDIM, 128, 0);

    // join residual half, then layer-2 aggregation with fused W3 dot
    cudaStreamWaitEvent(0, evB, 0);
    k_spmm2<<<gWarp, 256>>>(pH2, pHR, W3, N);

    // final aggregation (scalar per node)
    k_spmm3<<<gN256, 256>>>(out, b3, N);
}

// round 16
// speedup vs baseline: 1.8073x; 1.0731x over previous
#include <cuda_runtime.h>
#include <cuda_bf16.h>
#include <cuda_fp16.h>
#include <cstdint>

// ---------------- problem constants ----------------
#define MAXN 100000
#define MAXE 1600000
#define HDIM 128
#define VDIM 256
#define BN_EPS 1e-5f

// ---------------- device scratch (static; no cudaMalloc) --------
__device__ float d_deg[MAXN];
__device__ float d_dis[MAXN];
__device__ float d_self[MAXN];
__device__ int   d_cnt[MAXN];
__device__ int   d_rowptr[MAXN];
__device__ int   d_cursor[MAXN];
__device__ int2  d_edge[MAXE];
__device__ int   d_bsums[128];
__device__ int   d_is64;
__device__ __half d_H1h[(size_t)MAXN * HDIM];  // layer-1 GEMM out, fp16 (gathered)
__device__ __half d_H2h[(size_t)MAXN * HDIM];  // layer-2 GEMM out, fp16 (gathered)
__device__ float  d_RES[(size_t)MAXN * HDIM];  // x @ Wres, fp32 (streamed once)
__device__ float d_t  [MAXN];
__device__ float d_sc1[HDIM], d_sh1[HDIM], d_sc2[HDIM], d_sh2[HDIM];
// bf16 split operands
__device__ __nv_bfloat16 d_xhi[(size_t)MAXN * VDIM];
__device__ __nv_bfloat16 d_xlo[(size_t)MAXN * VDIM];
__device__ __nv_bfloat16 d_Ahi[(size_t)MAXN * HDIM];
__device__ __nv_bfloat16 d_Alo[(size_t)MAXN * HDIM];
__device__ __nv_bfloat16 d_W1hi[256 * 256], d_W1lo[256 * 256];   // [n][k] = [W1|Wres]^T
__device__ __nv_bfloat16 d_W2hi[128 * 128], d_W2lo[128 * 128];   // [n][k] = W2^T

// ---------------- PTX helpers (all baseline sm_80+ features) -----------------
__device__ __forceinline__ uint32_t smem_u32(const void* p) {
    uint32_t a;
    asm("{ .reg .u64 t; cvta.to.shared.u64 t, %1; cvt.u32.u64 %0, t; }"
        : "=r"(a) : "l"(p));
    return a;
}
__device__ __forceinline__ void ldm_x4(uint32_t a, uint32_t* r) {
    asm volatile("ldmatrix.sync.aligned.m8n8.x4.shared.b16 {%0,%1,%2,%3}, [%4];"
                 : "=r"(r[0]), "=r"(r[1]), "=r"(r[2]), "=r"(r[3]) : "r"(a));
}
__device__ __forceinline__ void mma16816(float* c, const uint32_t* a, const uint32_t* b) {
    asm volatile("mma.sync.aligned.m16n8k16.row.col.f32.bf16.bf16.f32 "
                 "{%0,%1,%2,%3}, {%4,%5,%6,%7}, {%8,%9}, {%0,%1,%2,%3};"
                 : "+f"(c[0]), "+f"(c[1]), "+f"(c[2]), "+f"(c[3])
                 : "r"(a[0]), "r"(a[1]), "r"(a[2]), "r"(a[3]), "r"(b[0]), "r"(b[1]));
}
__device__ __forceinline__ void cp16(uint32_t sa, const void* g) {
    asm volatile("cp.async.cg.shared.global [%0], [%1], 16;" :: "r"(sa), "l"(g));
}
__device__ __forceinline__ void cp_commit() {
    asm volatile("cp.async.commit_group;" ::: "memory");
}

__device__ __forceinline__ unsigned short bfbits(float f) {
    __nv_bfloat16 b = __float2bfloat16_rn(f);
    return *reinterpret_cast<unsigned short*>(&b);
}

// ---------------- edge_index dtype detection --------------------------------
__global__ void k_dtype(const void* ei, int E, int n) {
    __shared__ int bad;
    if (threadIdx.x == 0) bad = 0;
    __syncthreads();
    const long long* p = (const long long*)ei;
    int k = min(2 * E, 2048);
    for (int i = threadIdx.x; i < k; i += blockDim.x) {
        long long v = p[i];
        if (v < 0 || v >= (long long)n) bad = 1;
    }
    __syncthreads();
    if (threadIdx.x == 0) d_is64 = bad ? 0 : 1;
}
__device__ __forceinline__ int edge_at(const void* ei, size_t idx, int is64) {
    return is64 ? (int)((const long long*)ei)[idx] : ((const int*)ei)[idx];
}

// ---------------- graph preprocessing --------------------------------------
__global__ void k_init(int n) {
    int i = blockIdx.x * blockDim.x + threadIdx.x;
    if (i < n) { d_deg[i] = 1.0f; d_cnt[i] = 0; }
}
__global__ void k_degcnt(const void* __restrict__ ei, const float* __restrict__ ew, int E) {
    int e = blockIdx.x * blockDim.x + threadIdx.x;
    if (e < E) {
        int is64 = d_is64;
        int c = edge_at(ei, (size_t)E + e, is64);
        atomicAdd(&d_deg[c], ew[e]);
        atomicAdd(&d_cnt[c], 1);
    }
}
__global__ void k_dis(int n) {
    int i = blockIdx.x * blockDim.x + threadIdx.x;
    if (i < n) {
        float d = d_deg[i];
        d_dis[i] = rsqrtf(d);
        d_self[i] = 1.0f / d;
    }
}
__global__ void k_scan1(int n) {
    __shared__ int s[1024];
    int i = blockIdx.x * 1024 + threadIdx.x;
    int v = (i < n) ? d_cnt[i] : 0;
    s[threadIdx.x] = v;
    __syncthreads();
    for (int off = 1; off < 1024; off <<= 1) {
        int t = (threadIdx.x >= off) ? s[threadIdx.x - off] : 0;
        __syncthreads();
        s[threadIdx.x] += t;
        __syncthreads();
    }
    if (i < n) d_rowptr[i] = s[threadIdx.x] - v;
    if (threadIdx.x == 1023) d_bsums[blockIdx.x] = s[1023];
}
__global__ void k_scan2(int nb) {
    __shared__ int s[128];
    int t = threadIdx.x;
    int v = (t < nb) ? d_bsums[t] : 0;
    s[t] = v;
    __syncthreads();
    for (int off = 1; off < 128; off <<= 1) {
        int u = (t >= off) ? s[t - off] : 0;
        __syncthreads();
        s[t] += u;
        __syncthreads();
    }
    if (t < nb) d_bsums[t] = s[t] - v;
}
__global__ void k_scan3(int n) {
    int i = blockIdx.x * 1024 + threadIdx.x;
    if (i < n) {
        int r = d_rowptr[i] + d_bsums[blockIdx.x];
        d_rowptr[i] = r;
        d_cursor[i] = r;
    }
}
__global__ void k_fill(const void* __restrict__ ei, const float* __restrict__ ew, int E) {
    int e = blockIdx.x * blockDim.x + threadIdx.x;
    if (e < E) {
        int is64 = d_is64;
        int r = edge_at(ei, (size_t)e, is64);
        int c = edge_at(ei, (size_t)E + e, is64);
        int p = atomicAdd(&d_cursor[c], 1);
        float w = d_dis[r] * ew[e] * d_dis[c];
        d_edge[p] = make_int2(r, __float_as_int(w));
    }
}
__global__ void k_bnprep(const float* b1, const float* g1, const float* be1,
                         const float* m1, const float* v1,
                         const float* b2, const float* g2, const float* be2,
                         const float* m2, const float* v2) {
    int i = threadIdx.x;
    if (i < HDIM) {
        float s1 = g1[i] * rsqrtf(v1[i] + BN_EPS);
        d_sc1[i] = s1;
        d_sh1[i] = (b1[i] - m1[i]) * s1 + be1[i];
        float s2 = g2[i] * rsqrtf(v2[i] + BN_EPS);
        d_sc2[i] = s2;
        d_sh2[i] = (b2[i] - m2[i]) * s2 + be2[i];
    }
}

// ---------------- operand prep: fp32 -> bf16 hi/lo ---------------------------
__global__ void k_splitx(const float* __restrict__ x, size_t n4) {
    size_t i = (size_t)blockIdx.x * blockDim.x + threadIdx.x;
    if (i >= n4) return;
    float4 v = reinterpret_cast<const float4*>(x)[i];
    unsigned short h0 = bfbits(v.x), h1 = bfbits(v.y), h2 = bfbits(v.z), h3 = bfbits(v.w);
    __nv_bfloat16 b0 = *reinterpret_cast<__nv_bfloat16*>(&h0);
    __nv_bfloat16 b1 = *reinterpret_cast<__nv_bfloat16*>(&h1);
    __nv_bfloat16 b2 = *reinterpret_cast<__nv_bfloat16*>(&h2);
    __nv_bfloat16 b3 = *reinterpret_cast<__nv_bfloat16*>(&h3);
    unsigned short l0 = bfbits(v.x - __bfloat162float(b0));
    unsigned short l1 = bfbits(v.y - __bfloat162float(b1));
    unsigned short l2 = bfbits(v.z - __bfloat162float(b2));
    unsigned short l3 = bfbits(v.w - __bfloat162float(b3));
    uint2 hu = make_uint2((uint32_t)h0 | ((uint32_t)h1 << 16), (uint32_t)h2 | ((uint32_t)h3 << 16));
    uint2 lu = make_uint2((uint32_t)l0 | ((uint32_t)l1 << 16), (uint32_t)l2 | ((uint32_t)l3 << 16));
    reinterpret_cast<uint2*>(d_xhi)[i] = hu;
    reinterpret_cast<uint2*>(d_xlo)[i] = lu;
}
// W1|Wres -> transposed [n][k] (n<128: W1, n>=128: Wres), hi/lo
__global__ void k_prepw1(const float* __restrict__ W1, const float* __restrict__ Wres) {
    int i = blockIdx.x * blockDim.x + threadIdx.x;
    if (i >= 256 * 256) return;
    int n = i >> 8, k = i & 255;
    float w = (n < 128) ? W1[(size_t)k * 128 + n] : Wres[(size_t)k * 128 + (n - 128)];
    unsigned short h = bfbits(w);
    __nv_bfloat16 hb = *reinterpret_cast<__nv_bfloat16*>(&h);
    unsigned short l = bfbits(w - __bfloat162float(hb));
    d_W1hi[i] = hb;
    d_W1lo[i] = *reinterpret_cast<__nv_bfloat16*>(&l);
}
__global__ void k_prepw2(const float* __restrict__ W2) {
    int i = blockIdx.x * blockDim.x + threadIdx.x;
    if (i >= 128 * 128) return;
    int n = i >> 7, k = i & 127;
    float w = W2[(size_t)k * 128 + n];
    unsigned short h = bfbits(w);
    __nv_bfloat16 hb = *reinterpret_cast<__nv_bfloat16*>(&h);
    unsigned short l = bfbits(w - __bfloat162float(hb));
    d_W2hi[i] = hb;
    d_W2lo[i] = *reinterpret_cast<__nv_bfloat16*>(&l);
}

// ---------------- mma.sync split-bf16 GEMM -----------------------------------
// OUT=0: fp32 C; OUT=1: fp16 C  (Cstride in elements of the output type)
#define LDSB 144              // bytes per SMEM row (64 bf16 + 8 pad)
#define MATB 18432            // bytes per matrix (128 * 144)
#define STAGEB 73728          // 4 matrices
#define TG_SMEM (2 * STAGEB)  // 147456

template<int OUT>
__global__ __launch_bounds__(256)
void k_tgemm(const __nv_bfloat16* __restrict__ Ahi, const __nv_bfloat16* __restrict__ Alo,
             const __nv_bfloat16* __restrict__ Whi, const __nv_bfloat16* __restrict__ Wlo,
             void* __restrict__ Cout, int N, int K, int Cstride) {
    extern __shared__ char smem[];
    const uint32_t sbase = smem_u32(smem);
    const int tid = threadIdx.x;
    const int lane = tid & 31;
    const int wid = tid >> 5;
    const int m_w = (wid >> 2) * 64;
    const int n_w = (wid & 3) * 32;
    const int rowBase = blockIdx.x * 128;
    const int nBase = blockIdx.y * 128;
    const int nch = K >> 6;

    float acc[4][4][4];
#pragma unroll
    for (int a = 0; a < 4; a++)
#pragma unroll
        for (int b = 0; b < 4; b++)
#pragma unroll
            for (int c = 0; c < 4; c++) acc[a][b][c] = 0.0f;

    auto load_stage = [&](int buf, int k0) {
        uint32_t sb = sbase + buf * STAGEB;
#pragma unroll
        for (int i = 0; i < 16; i++) {
            int s = tid + i * 256;
            int m = s >> 10;           // 0:Ahi 1:Alo 2:Whi 3:Wlo
            int r = (s >> 3) & 127;
            int c = s & 7;
            const __nv_bfloat16* g;
            if (m == 0)      g = Ahi + (size_t)min(rowBase + r, N - 1) * K;
            else if (m == 1) g = Alo + (size_t)min(rowBase + r, N - 1) * K;
            else if (m == 2) g = Whi + (size_t)(nBase + r) * K;
            else             g = Wlo + (size_t)(nBase + r) * K;
            cp16(sb + m * MATB + r * LDSB + c * 16, g + k0 + c * 8);
        }
        cp_commit();
    };

    auto compute = [&](int buf) {
        uint32_t Ab = sbase + buf * STAGEB;
        uint32_t Wb = Ab + 2 * MATB;
#pragma unroll
        for (int kk = 0; kk < 64; kk += 16) {
            uint32_t ah[4][4], al[4][4], bh[2][4], bl[2][4];
#pragma unroll
            for (int mt = 0; mt < 4; mt++) {
                uint32_t ad = Ab + (m_w + mt * 16 + (lane & 15)) * LDSB
                                 + (kk + ((lane >> 4) << 3)) * 2;
                ldm_x4(ad, ah[mt]);
                ldm_x4(ad + MATB, al[mt]);
            }
#pragma unroll
            for (int p = 0; p < 2; p++) {
                int nloc = n_w + p * 16 + ((lane >> 4) << 3) + (lane & 7);
                uint32_t bd = Wb + nloc * LDSB + (kk + (((lane >> 3) & 1) << 3)) * 2;
                ldm_x4(bd, bh[p]);
                ldm_x4(bd + MATB, bl[p]);
            }
#pragma unroll
            for (int mt = 0; mt < 4; mt++)
#pragma unroll
                for (int nt = 0; nt < 4; nt++) {
                    const uint32_t* bhp = &bh[nt >> 1][(nt & 1) * 2];
                    const uint32_t* blp = &bl[nt >> 1][(nt & 1) * 2];
                    mma16816(acc[mt][nt], ah[mt], bhp);
                    mma16816(acc[mt][nt], al[mt], bhp);
                    mma16816(acc[mt][nt], ah[mt], blp);
                }
        }
    };

    load_stage(0, 0);
    if (nch > 1) load_stage(1, 64);

    for (int c = 0; c < nch; c++) {
        if (c + 1 == nch) asm volatile("cp.async.wait_group 0;" ::: "memory");
        else              asm volatile("cp.async.wait_group 1;" ::: "memory");
        __syncthreads();
        compute(c & 1);
        __syncthreads();
        if (c + 2 < nch) load_stage(c & 1, (c + 2) * 64);
    }

#pragma unroll
    for (int mt = 0; mt < 4; mt++) {
#pragma unroll
        for (int nt = 0; nt < 4; nt++) {
            int row0 = rowBase + m_w + mt * 16 + (lane >> 2);
            int col = nBase + n_w + nt * 8 + (lane & 3) * 2;
            if (OUT == 0) {
                float* C = (float*)Cout;
                if (row0 < N)
                    *reinterpret_cast<float2*>(&C[(size_t)row0 * Cstride + col]) =
                        make_float2(acc[mt][nt][0], acc[mt][nt][1]);
                if (row0 + 8 < N)
                    *reinterpret_cast<float2*>(&C[(size_t)(row0 + 8) * Cstride + col]) =
                        make_float2(acc[mt][nt][2], acc[mt][nt][3]);
            } else {
                __half* C = (__half*)Cout;
                if (row0 < N)
                    *reinterpret_cast<__half2*>(&C[(size_t)row0 * Cstride + col]) =
                        __floats2half2_rn(acc[mt][nt][0], acc[mt][nt][1]);
                if (row0 + 8 < N)
                    *reinterpret_cast<__half2*>(&C[(size_t)(row0 + 8) * Cstride + col]) =
                        __floats2half2_rn(acc[mt][nt][2], acc[mt][nt][3]);
            }
        }
    }
}

// ---------------- SpMM layer 1: fp16 H1 gather -> relu(bn) -> bf16 hi/lo -----
__global__ __launch_bounds__(256)
void k_spmm1(const __half* __restrict__ H1, int N) {
    int node = (blockIdx.x * blockDim.x + threadIdx.x) >> 5;
    int lane = threadIdx.x & 31;
    if (node >= N) return;
    const uint2* Hp = reinterpret_cast<const uint2*>(H1);   // 32 x 8B per row

    float sn = d_self[node];
    uint2 sv = Hp[(size_t)node * 32 + lane];
    float2 f0 = __half22float2(*reinterpret_cast<__half2*>(&sv.x));
    float2 f1 = __half22float2(*reinterpret_cast<__half2*>(&sv.y));
    float ax = f0.x * sn, ay = f0.y * sn, az = f1.x * sn, aw = f1.y * sn;

    int p = d_rowptr[node];
    int e = p + d_cnt[node];
    for (; p < e; p++) {
        int2 ed = d_edge[p];
        float w = __int_as_float(ed.y);
        uint2 v = Hp[(size_t)ed.x * 32 + lane];
        float2 g0 = __half22float2(*reinterpret_cast<__half2*>(&v.x));
        float2 g1 = __half22float2(*reinterpret_cast<__half2*>(&v.y));
        ax = fmaf(g0.x, w, ax); ay = fmaf(g0.y, w, ay);
        az = fmaf(g1.x, w, az); aw = fmaf(g1.y, w, aw);
    }
    float4 s4 = *reinterpret_cast<const float4*>(&d_sc1[lane * 4]);
    float4 h4 = *reinterpret_cast<const float4*>(&d_sh1[lane * 4]);
    float o0 = fmaxf(fmaf(ax, s4.x, h4.x), 0.f);
    float o1 = fmaxf(fmaf(ay, s4.y, h4.y), 0.f);
    float o2 = fmaxf(fmaf(az, s4.z, h4.z), 0.f);
    float o3 = fmaxf(fmaf(aw, s4.w, h4.w), 0.f);

    unsigned short h0 = bfbits(o0), h1 = bfbits(o1), h2 = bfbits(o2), h3 = bfbits(o3);
    __nv_bfloat16 b0 = *reinterpret_cast<__nv_bfloat16*>(&h0);
    __nv_bfloat16 b1 = *reinterpret_cast<__nv_bfloat16*>(&h1);
    __nv_bfloat16 b2 = *reinterpret_cast<__nv_bfloat16*>(&h2);
    __nv_bfloat16 b3 = *reinterpret_cast<__nv_bfloat16*>(&h3);
    unsigned short l0 = bfbits(o0 - __bfloat162float(b0));
    unsigned short l1 = bfbits(o1 - __bfloat162float(b1));
    unsigned short l2 = bfbits(o2 - __bfloat162float(b2));
    unsigned short l3 = bfbits(o3 - __bfloat162float(b3));
    size_t oi = (size_t)node * 32 + lane;
    reinterpret_cast<uint2*>(d_Ahi)[oi] =
        make_uint2((uint32_t)h0 | ((uint32_t)h1 << 16), (uint32_t)h2 | ((uint32_t)h3 << 16));
    reinterpret_cast<uint2*>(d_Alo)[oi] =
        make_uint2((uint32_t)l0 | ((uint32_t)l1 << 16), (uint32_t)l2 | ((uint32_t)l3 << 16));
}

// ---- SpMM layer 2 + fused head: fp16 H2 gather + res -> bn/relu -> dot(W3) --
__global__ __launch_bounds__(256)
void k_spmm2(const __half* __restrict__ H2, const float* __restrict__ RES,
             const float* __restrict__ W3, int N) {
    int node = (blockIdx.x * blockDim.x + threadIdx.x) >> 5;
    int lane = threadIdx.x & 31;
    if (node >= N) return;
    const uint2* Hp = reinterpret_cast<const uint2*>(H2);

    float sn = d_self[node];
    uint2 sv = Hp[(size_t)node * 32 + lane];
    float2 f0 = __half22float2(*reinterpret_cast<__half2*>(&sv.x));
    float2 f1 = __half22float2(*reinterpret_cast<__half2*>(&sv.y));
    float ax = f0.x * sn, ay = f0.y * sn, az = f1.x * sn, aw = f1.y * sn;

    int p = d_rowptr[node];
    int e = p + d_cnt[node];
    for (; p < e; p++) {
        int2 ed = d_edge[p];
        float w = __int_as_float(ed.y);
        uint2 v = Hp[(size_t)ed.x * 32 + lane];
        float2 g0 = __half22float2(*reinterpret_cast<__half2*>(&v.x));
        float2 g1 = __half22float2(*reinterpret_cast<__half2*>(&v.y));
        ax = fmaf(g0.x, w, ax); ay = fmaf(g0.y, w, ay);
        az = fmaf(g1.x, w, az); aw = fmaf(g1.y, w, aw);
    }
    float4 r = reinterpret_cast<const float4*>(RES)[(size_t)node * 32 + lane];
    ax += r.x; ay += r.y; az += r.z; aw += r.w;

    float4 s4 = *reinterpret_cast<const float4*>(&d_sc2[lane * 4]);
    float4 h4 = *reinterpret_cast<const float4*>(&d_sh2[lane * 4]);
    float o0 = fmaxf(fmaf(ax, s4.x, h4.x), 0.f);
    float o1 = fmaxf(fmaf(ay, s4.y, h4.y), 0.f);
    float o2 = fmaxf(fmaf(az, s4.z, h4.z), 0.f);
    float o3 = fmaxf(fmaf(aw, s4.w, h4.w), 0.f);

    float4 w3 = reinterpret_cast<const float4*>(W3)[lane];
    float s = o0 * w3.x + o1 * w3.y + o2 * w3.z + o3 * w3.w;
#pragma unroll
    for (int off = 16; off; off >>= 1) s += __shfl_down_sync(0xffffffffu, s, off);
    if (lane == 0) d_t[node] = s;
}

__global__ void k_spmm3(float* __restrict__ out, const float* __restrict__ b3, int N) {
    int i = blockIdx.x * blockDim.x + threadIdx.x;
    if (i >= N) return;
    float acc = d_t[i] * d_self[i];
    int p = d_rowptr[i];
    int e = p + d_cnt[i];
    for (; p < e; p++) {
        int2 ed = d_edge[p];
        acc = fmaf(d_t[ed.x], __int_as_float(ed.y), acc);
    }
    out[i] = acc + b3[0];
}

// ---------------- launch ------------------------------------------------------
extern "C" void kernel_launch(void* const* d_in, const int* in_sizes, int n_in,
                              void* d_out, int out_size) {
    const float* x    = (const float*)d_in[0];
    const void*  ei   = d_in[1];
    const float* ew   = (const float*)d_in[2];
    const float* W1   = (const float*)d_in[3];
    const float* b1   = (const float*)d_in[4];
    const float* W2   = (const float*)d_in[5];
    const float* b2   = (const float*)d_in[6];
    const float* W3   = (const float*)d_in[7];
    const float* b3   = (const float*)d_in[8];
    const float* Wres = (const float*)d_in[9];
    const float* g1 = (const float*)d_in[10];
    const float* be1 = (const float*)d_in[11];
    const float* m1 = (const float*)d_in[12];
    const float* v1 = (const float*)d_in[13];
    const float* g2 = (const float*)d_in[14];
    const float* be2 = (const float*)d_in[15];
    const float* m2 = (const float*)d_in[16];
    const float* v2 = (const float*)d_in[17];

    int N = out_size;
    int E = in_sizes[2];
    float* out = (float*)d_out;

    static cudaStream_t s_pre = nullptr, s_aux = nullptr;
    static cudaEvent_t evRoot = nullptr, evPre = nullptr, evA = nullptr, evB = nullptr;
    if (!s_pre) {
        cudaStreamCreateWithFlags(&s_pre, cudaStreamNonBlocking);
        cudaStreamCreateWithFlags(&s_aux, cudaStreamNonBlocking);
        cudaEventCreateWithFlags(&evRoot, cudaEventDisableTiming);
        cudaEventCreateWithFlags(&evPre,  cudaEventDisableTiming);
        cudaEventCreateWithFlags(&evA,    cudaEventDisableTiming);
        cudaEventCreateWithFlags(&evB,    cudaEventDisableTiming);
        cudaFuncSetAttribute(k_tgemm<0>, cudaFuncAttributeMaxDynamicSharedMemorySize, TG_SMEM);
        cudaFuncSetAttribute(k_tgemm<1>, cudaFuncAttributeMaxDynamicSharedMemorySize, TG_SMEM);
    }

    float *pRES;
    __half *pH1h, *pH2h;
    __nv_bfloat16 *pxhi, *pxlo, *pAhi, *pAlo, *pW1hi, *pW1lo, *pW2hi, *pW2lo;
    cudaGetSymbolAddress((void**)&pH1h,  d_H1h);
    cudaGetSymbolAddress((void**)&pH2h,  d_H2h);
    cudaGetSymbolAddress((void**)&pRES,  d_RES);
    cudaGetSymbolAddress((void**)&pxhi,  d_xhi);
    cudaGetSymbolAddress((void**)&pxlo,  d_xlo);
    cudaGetSymbolAddress((void**)&pAhi,  d_Ahi);
    cudaGetSymbolAddress((void**)&pAlo,  d_Alo);
    cudaGetSymbolAddress((void**)&pW1hi, d_W1hi);
    cudaGetSymbolAddress((void**)&pW1lo, d_W1lo);
    cudaGetSymbolAddress((void**)&pW2hi, d_W2hi);
    cudaGetSymbolAddress((void**)&pW2lo, d_W2lo);

    int nb    = (N + 1023) / 1024;
    int gN256 = (N + 255) / 256;
    int gE256 = (E + 255) / 256;
    int gWarp = (N + 7) / 8;
    int gRows = (N + 127) / 128;
    size_t n4 = (size_t)N * VDIM / 4;

    // ---- fork: preprocessing on s_pre; legacy does dense path ----
    cudaEventRecord(evRoot, 0);
    cudaStreamWaitEvent(s_pre, evRoot, 0);

    k_dtype <<<1, 256, 0, s_pre>>>(ei, E, N);
    k_init  <<<gN256, 256, 0, s_pre>>>(N);
    k_degcnt<<<gE256, 256, 0, s_pre>>>(ei, ew, E);
    k_dis   <<<gN256, 256, 0, s_pre>>>(N);
    k_scan1 <<<nb, 1024, 0, s_pre>>>(N);
    k_scan2 <<<1, 128, 0, s_pre>>>(nb);
    k_scan3 <<<nb, 1024, 0, s_pre>>>(N);
    k_fill  <<<gE256, 256, 0, s_pre>>>(ei, ew, E);
    k_bnprep<<<1, 128, 0, s_pre>>>(b1, g1, be1, m1, v1, b2, g2, be2, m2, v2);
    cudaEventRecord(evPre, s_pre);

    // legacy: operand prep then G1a at full machine width
    k_splitx<<<(int)((n4 + 255) / 256), 256>>>(x, n4);
    k_prepw1<<<(256 * 256 + 255) / 256, 256>>>(W1, Wres);
    k_prepw2<<<(128 * 128 + 255) / 256, 256>>>(W2);

    // G1a: x @ W1 -> H1 (fp16)
    k_tgemm<1><<<dim3(gRows, 1), 256, TG_SMEM>>>(pxhi, pxlo, pW1hi, pW1lo,
                                                 pH1h, N, VDIM, 128);
    cudaEventRecord(evA, 0);

    // s_aux: G1b (x @ Wres -> RES fp32) after G1a, overlapping SpMM-1
    cudaStreamWaitEvent(s_aux, evA, 0);
    k_tgemm<0><<<dim3(gRows, 1), 256, TG_SMEM, s_aux>>>(pxhi, pxlo,
                                                        pW1hi + 128 * 256, pW1lo + 128 * 256,
                                                        pRES, N, VDIM, 128);
    cudaEventRecord(evB, s_aux);

    // legacy: join preprocessing, then layer-1 aggregation
    cudaStreamWaitEvent(0, evPre, 0);
    k_spmm1<<<gWarp, 256>>>(pH1h, N);

    // layer 2 GEMM -> H2 (fp16)
    k_tgemm<1><<<dim3(gRows, 1), 256, TG_SMEM>>>(pAhi, pAlo, pW2hi, pW2lo,
                                                 pH2h, N, HDIM, 128);

    // join residual, then layer-2 aggregation with fused W3 dot
    cudaStreamWaitEvent(0, evB, 0);
    k_spmm2<<<gWarp, 256>>>(pH2h, pRES, W3, N);

    // final aggregation (scalar per node)
    k_spmm3<<<gN256, 256>>>(out, b3, N);
}